// round 1
// baseline (speedup 1.0000x reference)
#include <cuda_runtime.h>
#include <cfloat>
#include <math.h>

// ---------------- problem constants ----------------
#define NN   100000   // nodes
#define NE   800000   // edges
#define NC   20000    // clusters
#define NGE  320000   // global edges
#define NG   256      // graphs
#define EPSB 1e-5f

// ---------------- scratch (device globals; no allocation allowed) ----------------
__device__ float  g_h0[NN * 64];
__device__ float  g_agg[NN * 80];     // reused: 64-wide (L1), 80-wide (L2), 96-wide clusters
__device__ float  g_h1[NN * 80];
__device__ float  g_h2[NN * 96];
__device__ float  g_y [NC * 96];
__device__ float  g_y2[NC * 256];
__device__ int    g_ybatch[NC];
__device__ double g_stats[512];       // [0..255]=sum, [256..511]=sumsq
__device__ float  g_scale[256];
__device__ float  g_shift[256];

// ---------------- small utility kernels ----------------
__global__ void k_fill_f(float* p, float v, int n) {
    int i = blockIdx.x * blockDim.x + threadIdx.x;
    if (i < n) p[i] = v;
}
__global__ void k_fill_d(double* p, int n) {
    int i = blockIdx.x * blockDim.x + threadIdx.x;
    if (i < n) p[i] = 0.0;
}
__global__ void k_fill_i(int* p, int v, int n) {
    int i = blockIdx.x * blockDim.x + threadIdx.x;
    if (i < n) p[i] = v;
}

// h0[n][0:64] = emb[x[n]][0:64], float4-vectorized
__global__ void k_embed(const int* __restrict__ x, const float* __restrict__ emb,
                        float* __restrict__ h0) {
    int i = blockIdx.x * blockDim.x + threadIdx.x;   // NN*16
    if (i < NN * 16) {
        int n = i >> 4, q = i & 15;
        reinterpret_cast<float4*>(h0)[i] =
            reinterpret_cast<const float4*>(emb)[x[n] * 16 + q];
    }
}

// scatter-add: one warp per edge, lanes stride the feature dim
template <int D>
__global__ void k_scatter(const int* __restrict__ ei, int nE,
                          const float* __restrict__ src, float* __restrict__ agg) {
    int w = (blockIdx.x * blockDim.x + threadIdx.x) >> 5;
    int lane = threadIdx.x & 31;
    if (w >= nE) return;
    int s = ei[w];
    int d = ei[nE + w];
    const float* sp = src + (size_t)s * D;
    float*       dp = agg + (size_t)d * D;
#pragma unroll
    for (int f = lane; f < D; f += 32) atomicAdd(dp + f, sp[f]);
}

// ---------------- fused GEMM (+ relu, + BN statistics) ----------------
// out[N, MTOT] (cols [cbase, cbase+MCHUNK)) = relu( [agg | h] @ W^T + bias )
// z row = concat(agg[n][0:DAGG], h[n][0:DH]);  W is [MTOT][K] row-major, K = DAGG+DH.
// Block: 256 threads, 64-node tile; thread (tn = t&15, tm = t>>4)
// computes nodes {tn, tn+16, tn+32, tn+48} x outs {tm*OPT .. tm*OPT+OPT-1}.
template <int DAGG, int DH, int MTOT, int MCHUNK, bool STATS>
__global__ void __launch_bounds__(256)
k_gemm(const float* __restrict__ agg, const float* __restrict__ h,
       const float* __restrict__ W, const float* __restrict__ bias,
       float* __restrict__ out, int N, double* __restrict__ stats) {
    constexpr int K   = DAGG + DH;
    constexpr int NK  = K / 32;
    constexpr int OPT = MCHUNK / 16;
    static_assert(K % 32 == 0 && MCHUNK % 16 == 0, "tile shape");

    __shared__ float z_s[32][67];            // [kk][n]   (67: odd stride -> no conflicts)
    __shared__ float w_s[32][MCHUNK + 1];    // [kk][j]

    const int t     = threadIdx.x;
    const int tn    = t & 15;
    const int tm    = t >> 4;
    const int nbase = blockIdx.x * 64;
    const int cbase = blockIdx.y * MCHUNK;

    float acc[4][OPT];
#pragma unroll
    for (int i = 0; i < 4; ++i)
#pragma unroll
        for (int j = 0; j < OPT; ++j) acc[i][j] = 0.f;

    for (int c = 0; c < NK; ++c) {
        // --- load z tile (coalesced along k) ---
#pragma unroll
        for (int r = 0; r < 8; ++r) {
            int idx = t + r * 256;           // 0..2047
            int kk = idx & 31, n = idx >> 5;
            int node = nbase + n;
            int k = c * 32 + kk;
            float v = 0.f;
            if (node < N)
                v = (k < DAGG) ? agg[(size_t)node * DAGG + k]
                               : h[(size_t)node * DH + (k - DAGG)];
            z_s[kk][n] = v;
        }
        // --- load W tile (coalesced along k) ---
#pragma unroll
        for (int idx = t; idx < 32 * MCHUNK; idx += 256) {
            int kk = idx & 31, j = idx >> 5;
            w_s[kk][j] = W[(size_t)(cbase + j) * K + c * 32 + kk];
        }
        __syncthreads();

#pragma unroll 8
        for (int kk = 0; kk < 32; ++kk) {
            float zr[4];
#pragma unroll
            for (int i = 0; i < 4; ++i) zr[i] = z_s[kk][tn + 16 * i];
#pragma unroll
            for (int j = 0; j < OPT; ++j) {
                float wv = w_s[kk][tm * OPT + j];
#pragma unroll
                for (int i = 0; i < 4; ++i) acc[i][j] = fmaf(zr[i], wv, acc[i][j]);
            }
        }
        __syncthreads();
    }

    // --- epilogue: bias + relu + store + (optional) BN stats ---
#pragma unroll
    for (int j = 0; j < OPT; ++j) {
        int jg = cbase + tm * OPT + j;
        float bj = bias[jg];
        float s = 0.f, s2 = 0.f;
#pragma unroll
        for (int i = 0; i < 4; ++i) {
            int node = nbase + tn + 16 * i;
            if (node < N) {
                float v = fmaxf(acc[i][j] + bj, 0.f);
                out[(size_t)node * MTOT + jg] = v;
                s += v;
                s2 += v * v;
            }
        }
        if (STATS) {
#pragma unroll
            for (int off = 8; off; off >>= 1) {
                s  += __shfl_down_sync(0xffffffffu, s,  off, 16);
                s2 += __shfl_down_sync(0xffffffffu, s2, off, 16);
            }
            if (tn == 0) {
                atomicAdd(&stats[jg], (double)s);
                atomicAdd(&stats[256 + jg], (double)s2);
            }
        }
    }
}

// BN finalize: per-feature scale/shift from sum/sumsq (biased variance)
__global__ void k_bnfin(const double* __restrict__ stats, const float* __restrict__ g,
                        const float* __restrict__ be, float* __restrict__ scale,
                        float* __restrict__ shift, int M, int N) {
    int j = blockIdx.x * blockDim.x + threadIdx.x;
    if (j < M) {
        double inv = 1.0 / (double)N;
        float mean = (float)(stats[j] * inv);
        float var  = (float)(stats[256 + j] * inv) - mean * mean;
        float sc   = rsqrtf(var + EPSB) * g[j];
        scale[j] = sc;
        shift[j] = be[j] - mean * sc;
    }
}

__global__ void k_bnapply(float* __restrict__ h, const float* __restrict__ scale,
                          const float* __restrict__ shift, int total, int M) {
    int i = blockIdx.x * blockDim.x + threadIdx.x;
    if (i < total) {
        int j = i % M;
        h[i] = fmaf(h[i], scale[j], shift[j]);
    }
}

// signed-float atomic max via int/uint monotonic mapping
__device__ __forceinline__ void atomicMaxFloat(float* addr, float val) {
    if (val >= 0.f)
        atomicMax(reinterpret_cast<int*>(addr), __float_as_int(val));
    else
        atomicMin(reinterpret_cast<unsigned int*>(addr),
                  (unsigned int)__float_as_int(val));
}

__global__ void k_pool_max(const float* __restrict__ h2, const int* __restrict__ cluster,
                           float* __restrict__ y) {
    int i = blockIdx.x * blockDim.x + threadIdx.x;   // NN*96
    if (i < NN * 96) {
        int n = i / 96, f = i - n * 96;
        atomicMaxFloat(&y[cluster[n] * 96 + f], h2[i]);
    }
}

__global__ void k_pool_batch(const int* __restrict__ cluster, const int* __restrict__ batch,
                             int* __restrict__ ybatch) {
    int n = blockIdx.x * blockDim.x + threadIdx.x;
    if (n < NN) atomicMax(&ybatch[cluster[n]], batch[n]);
}

__global__ void k_final(const float* __restrict__ y2, const int* __restrict__ ybatch,
                        float* __restrict__ out) {
    int i = blockIdx.x * blockDim.x + threadIdx.x;   // NC*256
    if (i < NC * 256) {
        int c = i >> 8, f = i & 255;
        atomicMaxFloat(&out[ybatch[c] * 256 + f], y2[i]);
    }
}

// ---------------- launch ----------------
static inline int cdiv(int a, int b) { return (a + b - 1) / b; }

extern "C" void kernel_launch(void* const* d_in, const int* in_sizes, int n_in,
                              void* d_out, int out_size) {
    (void)in_sizes; (void)n_in; (void)out_size;
    const int*   x       = (const int*)d_in[0];
    const int*   ei      = (const int*)d_in[1];
    const int*   batch   = (const int*)d_in[2];
    const int*   cluster = (const int*)d_in[3];
    const int*   gei     = (const int*)d_in[4];
    const float* emb     = (const float*)d_in[5];
    const float* w1      = (const float*)d_in[6];
    const float* b1      = (const float*)d_in[7];
    const float* g1      = (const float*)d_in[8];
    const float* be1     = (const float*)d_in[9];
    const float* w2      = (const float*)d_in[10];
    const float* b2      = (const float*)d_in[11];
    const float* g2      = (const float*)d_in[12];
    const float* be2     = (const float*)d_in[13];
    const float* wm      = (const float*)d_in[14];
    const float* bm      = (const float*)d_in[15];
    float* out = (float*)d_out;

    float *h0, *agg, *h1, *h2, *y, *y2, *scale, *shift;
    int* ybatch;
    double* stats;
    cudaGetSymbolAddress((void**)&h0,     g_h0);
    cudaGetSymbolAddress((void**)&agg,    g_agg);
    cudaGetSymbolAddress((void**)&h1,     g_h1);
    cudaGetSymbolAddress((void**)&h2,     g_h2);
    cudaGetSymbolAddress((void**)&y,      g_y);
    cudaGetSymbolAddress((void**)&y2,     g_y2);
    cudaGetSymbolAddress((void**)&ybatch, g_ybatch);
    cudaGetSymbolAddress((void**)&stats,  g_stats);
    cudaGetSymbolAddress((void**)&scale,  g_scale);
    cudaGetSymbolAddress((void**)&shift,  g_shift);

    const int T = 256;

    // ---- layer 1: conv(64 -> 80) + BN ----
    k_fill_f<<<cdiv(NN * 64, T), T>>>(agg, 0.f, NN * 64);
    k_fill_d<<<2, T>>>(stats, 512);
    k_embed<<<cdiv(NN * 16, T), T>>>(x, emb, h0);
    k_scatter<64><<<cdiv(NE * 32, T), T>>>(ei, NE, h0, agg);
    {
        dim3 grid(cdiv(NN, 64), 1);
        k_gemm<64, 64, 80, 80, true><<<grid, T>>>(agg, h0, w1, b1, h1, NN, stats);
    }
    k_bnfin<<<1, 128>>>(stats, g1, be1, scale, shift, 80, NN);
    k_bnapply<<<cdiv(NN * 80, T), T>>>(h1, scale, shift, NN * 80, 80);

    // ---- layer 2: conv(80 -> 96) + BN ----
    k_fill_f<<<cdiv(NN * 80, T), T>>>(agg, 0.f, NN * 80);
    k_fill_d<<<2, T>>>(stats, 512);
    k_scatter<80><<<cdiv(NE * 32, T), T>>>(ei, NE, h1, agg);
    {
        dim3 grid(cdiv(NN, 64), 1);
        k_gemm<80, 80, 96, 96, true><<<grid, T>>>(agg, h1, w2, b2, h2, NN, stats);
    }
    k_bnfin<<<1, 128>>>(stats, g2, be2, scale, shift, 96, NN);
    k_bnapply<<<cdiv(NN * 96, T), T>>>(h2, scale, shift, NN * 96, 96);

    // ---- cluster max-pool ----
    k_fill_f<<<cdiv(NC * 96, T), T>>>(y, -FLT_MAX, NC * 96);
    k_fill_i<<<cdiv(NC, T), T>>>(ybatch, 0, NC);
    k_pool_max<<<cdiv(NN * 96, T), T>>>(h2, cluster, y);
    k_pool_batch<<<cdiv(NN, T), T>>>(cluster, batch, ybatch);

    // ---- global conv(96 -> 256), no BN ----
    k_fill_f<<<cdiv(NC * 96, T), T>>>(agg, 0.f, NC * 96);
    k_scatter<96><<<cdiv(NGE * 32, T), T>>>(gei, NGE, y, agg);
    {
        dim3 grid(cdiv(NC, 64), 2);   // 2 chunks of 128 output cols
        k_gemm<96, 96, 256, 128, false><<<grid, T>>>(agg, y, wm, bm, y2, NC, nullptr);
    }

    // ---- graph max-pool -> output ----
    k_fill_f<<<cdiv(NG * 256, T), T>>>(out, -FLT_MAX, NG * 256);
    k_final<<<cdiv(NC * 256, T), T>>>(y2, ybatch, out);
}

// round 2
// speedup vs baseline: 1.1327x; 1.1327x over previous
#include <cuda_runtime.h>
#include <cfloat>
#include <math.h>

// ---------------- problem constants ----------------
#define NN   100000   // nodes
#define NE   800000   // edges
#define NC   20000    // clusters
#define NGE  320000   // global edges
#define NG   256      // graphs
#define EPSB 1e-5f

// ---------------- scratch (device globals; no allocation allowed) ----------------
__device__ __align__(16) float  g_h0[NN * 64];
__device__ __align__(16) float  g_agg[NN * 80];
__device__ __align__(16) float  g_h1[NN * 80];
__device__ __align__(16) float  g_h2[NN * 96];
__device__ __align__(16) float  g_y [NC * 96];
__device__ __align__(16) float  g_y2[NC * 256];
__device__ int    g_ybatch[NC];
__device__ double g_stats[512];       // [0..255]=sum, [256..511]=sumsq
__device__ float  g_scale[256];
__device__ float  g_shift[256];

// ---------------- packed f32x2 helpers ----------------
typedef unsigned long long u64t;
__device__ __forceinline__ u64t pk2(float lo, float hi) {
    u64t r; asm("mov.b64 %0, {%1, %2};" : "=l"(r) : "f"(lo), "f"(hi)); return r;
}
__device__ __forceinline__ void upk2(float& lo, float& hi, u64t v) {
    asm("mov.b64 {%0, %1}, %2;" : "=f"(lo), "=f"(hi) : "l"(v));
}
__device__ __forceinline__ void fma2(u64t& d, u64t a, u64t b) {
    asm("fma.rn.f32x2 %0, %1, %2, %0;" : "+l"(d) : "l"(a), "l"(b));
}

// ---------------- small utility kernels ----------------
__global__ void k_fill_f4(float4* p, float v, int n4) {
    int i = blockIdx.x * blockDim.x + threadIdx.x;
    if (i < n4) p[i] = make_float4(v, v, v, v);
}
__global__ void k_fill_d(double* p, int n) {
    int i = blockIdx.x * blockDim.x + threadIdx.x;
    if (i < n) p[i] = 0.0;
}
__global__ void k_fill_i(int* p, int v, int n) {
    int i = blockIdx.x * blockDim.x + threadIdx.x;
    if (i < n) p[i] = v;
}

// h0[n][0:64] = emb[x[n]][0:64], float4-vectorized
__global__ void k_embed(const int* __restrict__ x, const float* __restrict__ emb,
                        float* __restrict__ h0) {
    int i = blockIdx.x * blockDim.x + threadIdx.x;   // NN*16
    if (i < NN * 16) {
        int n = i >> 4, q = i & 15;
        reinterpret_cast<float4*>(h0)[i] =
            reinterpret_cast<const float4*>(emb)[x[n] * 16 + q];
    }
}

// scatter-add via vector red: one thread per (edge, 16B chunk)
template <int D>
__global__ void k_scatter4(const int* __restrict__ ei, int nE,
                           const float* __restrict__ src, float* __restrict__ agg) {
    constexpr int F4 = D / 4;
    int gid = blockIdx.x * blockDim.x + threadIdx.x;
    int e = gid / F4;
    int f = gid - e * F4;
    if (e >= nE) return;
    int s = ei[e];
    int d = ei[nE + e];
    float4 v = reinterpret_cast<const float4*>(src + (size_t)s * D)[f];
    float* dp = agg + (size_t)d * D + f * 4;
    asm volatile("red.global.add.v4.f32 [%0], {%1, %2, %3, %4};"
                 :: "l"(dp), "f"(v.x), "f"(v.y), "f"(v.z), "f"(v.w) : "memory");
}

// ---------------- fused GEMM (+ relu, + BN statistics), packed f32x2 ----------------
// out[N, MTOT] (cols [cbase, cbase+MCHUNK)) = relu( [agg | h] @ W^T + bias )
// Block: 256 threads, 64-node tile; thread (tn = t&15, tm = t>>4) computes
// nodes {tn, tn+16, tn+32, tn+48} x outs {tm*OPT .. tm*OPT+OPT-1}, accumulated
// as f32x2 pairs: acc0 = nodes (tn, tn+16), acc1 = (tn+32, tn+48).
template <int DAGG, int DH, int MTOT, int MCHUNK, bool STATS>
__global__ void __launch_bounds__(256)
k_gemm(const float* __restrict__ agg, const float* __restrict__ h,
       const float* __restrict__ W, const float* __restrict__ bias,
       float* __restrict__ out, int N, double* __restrict__ stats) {
    constexpr int K   = DAGG + DH;
    constexpr int NK  = K / 32;
    constexpr int OPT = MCHUNK / 16;
    constexpr int ZS  = 66;               // z row stride in floats: [kk][tn*4 + i], 8B-aligned, low write conflict
    static_assert(K % 32 == 0 && MCHUNK % 16 == 0, "tile shape");

    __shared__ float z_s[32 * ZS];
    __shared__ float w_s[32][MCHUNK + 2];

    const int t     = threadIdx.x;
    const int tn    = t & 15;
    const int tm    = t >> 4;
    const int nbase = blockIdx.x * 64;
    const int cbase = blockIdx.y * MCHUNK;

    u64t acc0[OPT], acc1[OPT];
#pragma unroll
    for (int j = 0; j < OPT; ++j) { acc0[j] = 0ull; acc1[j] = 0ull; }

    for (int c = 0; c < NK; ++c) {
        // --- load z tile: z value for (node nbase+n, k = c*32+kk) at z_s[kk*ZS + (n&15)*4 + (n>>4)] ---
#pragma unroll
        for (int r = 0; r < 8; ++r) {
            int idx = t + r * 256;           // 0..2047
            int kk = idx & 31, n = idx >> 5;
            int node = nbase + n;
            int k = c * 32 + kk;
            float v = 0.f;
            if (node < N)
                v = (k < DAGG) ? agg[(size_t)node * DAGG + k]
                               : h[(size_t)node * DH + (k - DAGG)];
            z_s[kk * ZS + (n & 15) * 4 + (n >> 4)] = v;
        }
        // --- load W tile (coalesced along k) ---
#pragma unroll
        for (int idx = t; idx < 32 * MCHUNK; idx += 256) {
            int kk = idx & 31, j = idx >> 5;
            w_s[kk][j] = W[(size_t)(cbase + j) * K + c * 32 + kk];
        }
        __syncthreads();

#pragma unroll 8
        for (int kk = 0; kk < 32; ++kk) {
            const float* zp = &z_s[kk * ZS + tn * 4];
            u64t z0 = *reinterpret_cast<const u64t*>(zp);       // nodes tn, tn+16
            u64t z1 = *reinterpret_cast<const u64t*>(zp + 2);   // nodes tn+32, tn+48
#pragma unroll
            for (int j = 0; j < OPT; ++j) {
                float wv = w_s[kk][tm * OPT + j];
                u64t wb = pk2(wv, wv);
                fma2(acc0[j], z0, wb);
                fma2(acc1[j], z1, wb);
            }
        }
        __syncthreads();
    }

    // --- epilogue: bias + relu + store + (optional) BN stats ---
#pragma unroll
    for (int j = 0; j < OPT; ++j) {
        int jg = cbase + tm * OPT + j;
        float bj = bias[jg];
        float v[4];
        upk2(v[0], v[1], acc0[j]);
        upk2(v[2], v[3], acc1[j]);
        float s = 0.f, s2 = 0.f;
#pragma unroll
        for (int i = 0; i < 4; ++i) {
            int node = nbase + tn + 16 * i;
            if (node < N) {
                float r = fmaxf(v[i] + bj, 0.f);
                out[(size_t)node * MTOT + jg] = r;
                s += r;
                s2 += r * r;
            }
        }
        if (STATS) {
#pragma unroll
            for (int off = 8; off; off >>= 1) {
                s  += __shfl_down_sync(0xffffffffu, s,  off, 16);
                s2 += __shfl_down_sync(0xffffffffu, s2, off, 16);
            }
            if (tn == 0) {
                atomicAdd(&stats[jg], (double)s);
                atomicAdd(&stats[256 + jg], (double)s2);
            }
        }
    }
}

// BN finalize: per-feature scale/shift from sum/sumsq (biased variance)
__global__ void k_bnfin(const double* __restrict__ stats, const float* __restrict__ g,
                        const float* __restrict__ be, float* __restrict__ scale,
                        float* __restrict__ shift, int M, int N) {
    int j = blockIdx.x * blockDim.x + threadIdx.x;
    if (j < M) {
        double inv = 1.0 / (double)N;
        float mean = (float)(stats[j] * inv);
        float var  = (float)(stats[256 + j] * inv) - mean * mean;
        float sc   = rsqrtf(var + EPSB) * g[j];
        scale[j] = sc;
        shift[j] = be[j] - mean * sc;
    }
}

// BN apply, float4-vectorized. M4 = M/4 float4s per row.
__global__ void k_bnapply4(float4* __restrict__ h, const float4* __restrict__ scale4,
                           const float4* __restrict__ shift4, int total4, int M4) {
    int i = blockIdx.x * blockDim.x + threadIdx.x;
    if (i < total4) {
        int j = i % M4;
        float4 v = h[i];
        float4 sc = scale4[j];
        float4 sh = shift4[j];
        v.x = fmaf(v.x, sc.x, sh.x);
        v.y = fmaf(v.y, sc.y, sh.y);
        v.z = fmaf(v.z, sc.z, sh.z);
        v.w = fmaf(v.w, sc.w, sh.w);
        h[i] = v;
    }
}

// signed-float atomic max via int/uint monotonic mapping
__device__ __forceinline__ void atomicMaxFloat(float* addr, float val) {
    if (val >= 0.f)
        atomicMax(reinterpret_cast<int*>(addr), __float_as_int(val));
    else
        atomicMin(reinterpret_cast<unsigned int*>(addr),
                  (unsigned int)__float_as_int(val));
}

__global__ void k_pool_max(const float* __restrict__ h2, const int* __restrict__ cluster,
                           float* __restrict__ y) {
    int i = blockIdx.x * blockDim.x + threadIdx.x;   // NN*96
    if (i < NN * 96) {
        int n = i / 96, f = i - n * 96;
        atomicMaxFloat(&y[cluster[n] * 96 + f], h2[i]);
    }
}

__global__ void k_pool_batch(const int* __restrict__ cluster, const int* __restrict__ batch,
                             int* __restrict__ ybatch) {
    int n = blockIdx.x * blockDim.x + threadIdx.x;
    if (n < NN) atomicMax(&ybatch[cluster[n]], batch[n]);
}

__global__ void k_final(const float* __restrict__ y2, const int* __restrict__ ybatch,
                        float* __restrict__ out) {
    int i = blockIdx.x * blockDim.x + threadIdx.x;   // NC*256
    if (i < NC * 256) {
        int c = i >> 8, f = i & 255;
        atomicMaxFloat(&out[ybatch[c] * 256 + f], y2[i]);
    }
}

// ---------------- launch ----------------
static inline int cdiv(int a, int b) { return (a + b - 1) / b; }

extern "C" void kernel_launch(void* const* d_in, const int* in_sizes, int n_in,
                              void* d_out, int out_size) {
    (void)in_sizes; (void)n_in; (void)out_size;
    const int*   x       = (const int*)d_in[0];
    const int*   ei      = (const int*)d_in[1];
    const int*   batch   = (const int*)d_in[2];
    const int*   cluster = (const int*)d_in[3];
    const int*   gei     = (const int*)d_in[4];
    const float* emb     = (const float*)d_in[5];
    const float* w1      = (const float*)d_in[6];
    const float* b1      = (const float*)d_in[7];
    const float* g1      = (const float*)d_in[8];
    const float* be1     = (const float*)d_in[9];
    const float* w2      = (const float*)d_in[10];
    const float* b2      = (const float*)d_in[11];
    const float* g2      = (const float*)d_in[12];
    const float* be2     = (const float*)d_in[13];
    const float* wm      = (const float*)d_in[14];
    const float* bm      = (const float*)d_in[15];
    float* out = (float*)d_out;

    float *h0, *agg, *h1, *h2, *y, *y2, *scale, *shift;
    int* ybatch;
    double* stats;
    cudaGetSymbolAddress((void**)&h0,     g_h0);
    cudaGetSymbolAddress((void**)&agg,    g_agg);
    cudaGetSymbolAddress((void**)&h1,     g_h1);
    cudaGetSymbolAddress((void**)&h2,     g_h2);
    cudaGetSymbolAddress((void**)&y,      g_y);
    cudaGetSymbolAddress((void**)&y2,     g_y2);
    cudaGetSymbolAddress((void**)&ybatch, g_ybatch);
    cudaGetSymbolAddress((void**)&stats,  g_stats);
    cudaGetSymbolAddress((void**)&scale,  g_scale);
    cudaGetSymbolAddress((void**)&shift,  g_shift);

    const int T = 256;

    // ---- layer 1: conv(64 -> 80) + BN ----
    k_fill_f4<<<cdiv(NN * 16, T), T>>>((float4*)agg, 0.f, NN * 16);
    k_fill_d<<<2, T>>>(stats, 512);
    k_embed<<<cdiv(NN * 16, T), T>>>(x, emb, h0);
    k_scatter4<64><<<cdiv(NE * 16, T), T>>>(ei, NE, h0, agg);
    {
        dim3 grid(cdiv(NN, 64), 1);
        k_gemm<64, 64, 80, 80, true><<<grid, T>>>(agg, h0, w1, b1, h1, NN, stats);
    }
    k_bnfin<<<1, 128>>>(stats, g1, be1, scale, shift, 80, NN);
    k_bnapply4<<<cdiv(NN * 20, T), T>>>((float4*)h1, (const float4*)scale,
                                        (const float4*)shift, NN * 20, 20);

    // ---- layer 2: conv(80 -> 96) + BN ----
    k_fill_f4<<<cdiv(NN * 20, T), T>>>((float4*)agg, 0.f, NN * 20);
    k_fill_d<<<2, T>>>(stats, 512);
    k_scatter4<80><<<cdiv(NE * 20, T), T>>>(ei, NE, h1, agg);
    {
        dim3 grid(cdiv(NN, 64), 1);
        k_gemm<80, 80, 96, 96, true><<<grid, T>>>(agg, h1, w2, b2, h2, NN, stats);
    }
    k_bnfin<<<1, 128>>>(stats, g2, be2, scale, shift, 96, NN);
    k_bnapply4<<<cdiv(NN * 24, T), T>>>((float4*)h2, (const float4*)scale,
                                        (const float4*)shift, NN * 24, 24);

    // ---- cluster max-pool ----
    k_fill_f4<<<cdiv(NC * 24, T), T>>>((float4*)y, -FLT_MAX, NC * 24);
    k_fill_i<<<cdiv(NC, T), T>>>(ybatch, 0, NC);
    k_pool_max<<<cdiv(NN * 96, T), T>>>(h2, cluster, y);
    k_pool_batch<<<cdiv(NN, T), T>>>(cluster, batch, ybatch);

    // ---- global conv(96 -> 256), no BN ----
    k_fill_f4<<<cdiv(NC * 24, T), T>>>((float4*)agg, 0.f, NC * 24);
    k_scatter4<96><<<cdiv(NGE * 24, T), T>>>(gei, NGE, y, agg);
    {
        dim3 grid(cdiv(NC, 64), 2);   // 2 chunks of 128 output cols
        k_gemm<96, 96, 256, 128, false><<<grid, T>>>(agg, y, wm, bm, y2, NC, nullptr);
    }

    // ---- graph max-pool -> output ----
    k_fill_f4<<<cdiv(NG * 64, T), T>>>((float4*)out, -FLT_MAX, NG * 64);
    k_final<<<cdiv(NC * 256, T), T>>>(y2, ybatch, out);
}

// round 4
// speedup vs baseline: 1.3241x; 1.1689x over previous
#include <cuda_runtime.h>
#include <cfloat>
#include <math.h>

// ---------------- problem constants ----------------
#define NN   100000   // nodes
#define NE   800000   // edges
#define NC   20000    // clusters
#define NGE  320000   // global edges
#define NG   256      // graphs
#define EPSB 1e-5f

// ---------------- scratch (device globals) ----------------
__device__ __align__(16) float  g_h0[NN * 64];
__device__ __align__(16) float  g_agg[NN * 96];
__device__ __align__(16) float  g_h1[NN * 80];
__device__ __align__(16) float  g_h2[NN * 96];
__device__ __align__(16) float  g_y [NC * 96];
__device__ __align__(16) float  g_y2[NC * 256];
__device__ __align__(16) int    g_cnt[NN];
__device__ __align__(16) int    g_rowptr[NN + 1];
__device__ __align__(16) int    g_cur[NN];
__device__ __align__(16) int    g_colidx[NE];
__device__ __align__(16) int    g_growptr[NC + 1];
__device__ __align__(16) int    g_gcolidx[NGE];
__device__ int    g_nstart[NC + 1];
__device__ int    g_gstart[NG + 1];
__device__ int    g_ybatch[NC];
__device__ int    g_psum[128];
__device__ int    g_poff[128];
__device__ double g_stats[512];       // [0..255]=sum, [256..511]=sumsq
__device__ float  g_scale[256];
__device__ float  g_shift[256];

// ---------------- packed f32x2 helpers ----------------
typedef unsigned long long u64t;
__device__ __forceinline__ u64t pk2(float lo, float hi) {
    u64t r; asm("mov.b64 %0, {%1, %2};" : "=l"(r) : "f"(lo), "f"(hi)); return r;
}
__device__ __forceinline__ void upk2(float& lo, float& hi, u64t v) {
    asm("mov.b64 {%0, %1}, %2;" : "=f"(lo), "=f"(hi) : "l"(v));
}
__device__ __forceinline__ void fma2(u64t& d, u64t a, u64t b) {
    asm("fma.rn.f32x2 %0, %1, %2, %0;" : "+l"(d) : "l"(a), "l"(b));
}

// ---------------- tiny utility kernels ----------------
__global__ void k_fill_i(int* p, int v, int n) {
    int i = blockIdx.x * blockDim.x + threadIdx.x;
    if (i < n) p[i] = v;
}
__global__ void k_fill_d(double* p, int n) {
    int i = blockIdx.x * blockDim.x + threadIdx.x;
    if (i < n) p[i] = 0.0;
}

// ---------------- CSR build: histogram -> scan -> ticket ----------------
__global__ void k_hist(const int* __restrict__ dst, int nE, int* __restrict__ cnt) {
    int i = blockIdx.x * blockDim.x + threadIdx.x;
    if (i < nE) atomicAdd(&cnt[dst[i]], 1);
}

// per-1024-chunk exclusive scan (local), block sums to psum
__global__ void k_scan1(const int* __restrict__ cnt, int* __restrict__ loc,
                        int* __restrict__ psum, int n) {
    __shared__ int sh[256];
    int t = threadIdx.x;
    int idx = blockIdx.x * 1024 + t * 4;
    int a0 = 0, a1 = 0, a2 = 0, a3 = 0;
    if (idx + 3 < n) {
        int4 q = *reinterpret_cast<const int4*>(cnt + idx);
        a0 = q.x; a1 = q.y; a2 = q.z; a3 = q.w;
    } else {
        if (idx     < n) a0 = cnt[idx];
        if (idx + 1 < n) a1 = cnt[idx + 1];
        if (idx + 2 < n) a2 = cnt[idx + 2];
    }
    int s = a0 + a1 + a2 + a3;
    sh[t] = s; __syncthreads();
    for (int off = 1; off < 256; off <<= 1) {
        int u = (t >= off) ? sh[t - off] : 0;
        __syncthreads(); sh[t] += u; __syncthreads();
    }
    int excl = sh[t] - s;
    if (idx     < n) loc[idx]     = excl;
    if (idx + 1 < n) loc[idx + 1] = excl + a0;
    if (idx + 2 < n) loc[idx + 2] = excl + a0 + a1;
    if (idx + 3 < n) loc[idx + 3] = excl + a0 + a1 + a2;
    if (t == 255) psum[blockIdx.x] = sh[t];
}

__global__ void k_scan2(const int* __restrict__ psum, int* __restrict__ poff, int nb) {
    __shared__ int sh[128];
    int t = threadIdx.x;
    int v = (t < nb) ? psum[t] : 0;
    sh[t] = v; __syncthreads();
    for (int off = 1; off < 128; off <<= 1) {
        int u = (t >= off) ? sh[t - off] : 0;
        __syncthreads(); sh[t] += u; __syncthreads();
    }
    if (t < nb) poff[t] = sh[t] - v;
}

__global__ void k_scan3(int* __restrict__ rowptr, int* __restrict__ cur,
                        const int* __restrict__ poff, int n, int total) {
    int i = blockIdx.x * blockDim.x + threadIdx.x;
    if (i < n) {
        int v = rowptr[i] + poff[i >> 10];
        rowptr[i] = v;
        cur[i] = v;
    }
    if (i == 0) rowptr[n] = total;
}

__global__ void k_ticket(const int* __restrict__ ei, int nE,
                         int* __restrict__ cur, int* __restrict__ colidx) {
    int e = blockIdx.x * blockDim.x + threadIdx.x;
    if (e < nE) {
        int s = ei[e];
        int d = ei[nE + e];
        int p = atomicAdd(&cur[d], 1);
        colidx[p] = s;
    }
}

// ---------------- gather aggregations (warp per node, register acc) ----------------
// agg1[n] = sum over in-edges of emb[x[src]] (emb is L1-resident, 32KB)
__global__ void k_gather_emb(const int* __restrict__ rowptr, const int* __restrict__ colidx,
                             const int* __restrict__ x, const float* __restrict__ emb,
                             float* __restrict__ agg) {
    int w = (blockIdx.x * blockDim.x + threadIdx.x) >> 5;
    int lane = threadIdx.x & 31;
    if (w >= NN) return;
    int s0 = rowptr[w], s1 = rowptr[w + 1];
    float a0 = 0.f, a1 = 0.f;
    int e = s0;
    for (; e + 1 < s1; e += 2) {
        const float* r0 = emb + x[colidx[e]] * 64;
        const float* r1 = emb + x[colidx[e + 1]] * 64;
        a0 += r0[lane] + r1[lane];
        a1 += r0[lane + 32] + r1[lane + 32];
    }
    if (e < s1) {
        const float* r = emb + x[colidx[e]] * 64;
        a0 += r[lane]; a1 += r[lane + 32];
    }
    agg[(size_t)w * 64 + lane] = a0;
    agg[(size_t)w * 64 + lane + 32] = a1;
}

// agg2[n] = scale * (sum h1[src]) + deg * shift  (BN1 fold; D=80)
__global__ void k_gather_bn80(const int* __restrict__ rowptr, const int* __restrict__ colidx,
                              const float* __restrict__ h1, const float* __restrict__ scale,
                              const float* __restrict__ shift, float* __restrict__ agg) {
    int w = (blockIdx.x * blockDim.x + threadIdx.x) >> 5;
    int lane = threadIdx.x & 31;
    if (w >= NN) return;
    int s0 = rowptr[w], s1 = rowptr[w + 1];
    float a0 = 0.f, a1 = 0.f, a2 = 0.f;
    int e = s0;
    for (; e + 1 < s1; e += 2) {
        const float* r0 = h1 + (size_t)colidx[e] * 80;
        const float* r1 = h1 + (size_t)colidx[e + 1] * 80;
        a0 += r0[lane] + r1[lane];
        a1 += r0[lane + 32] + r1[lane + 32];
        if (lane < 16) a2 += r0[lane + 64] + r1[lane + 64];
    }
    if (e < s1) {
        const float* r = h1 + (size_t)colidx[e] * 80;
        a0 += r[lane]; a1 += r[lane + 32];
        if (lane < 16) a2 += r[lane + 64];
    }
    float deg = (float)(s1 - s0);
    float* dp = agg + (size_t)w * 80;
    dp[lane]      = fmaf(a0, scale[lane],      deg * shift[lane]);
    dp[lane + 32] = fmaf(a1, scale[lane + 32], deg * shift[lane + 32]);
    if (lane < 16)
        dp[lane + 64] = fmaf(a2, scale[lane + 64], deg * shift[lane + 64]);
}

// agg3[c] = sum y[src]  (D=96, y already BN'd)
__global__ void k_gather96(const int* __restrict__ rowptr, const int* __restrict__ colidx,
                           const float* __restrict__ src, float* __restrict__ agg, int N) {
    int w = (blockIdx.x * blockDim.x + threadIdx.x) >> 5;
    int lane = threadIdx.x & 31;
    if (w >= N) return;
    int s0 = rowptr[w], s1 = rowptr[w + 1];
    float a0 = 0.f, a1 = 0.f, a2 = 0.f;
    int e = s0;
    for (; e + 1 < s1; e += 2) {
        const float* r0 = src + (size_t)colidx[e] * 96;
        const float* r1 = src + (size_t)colidx[e + 1] * 96;
        a0 += r0[lane] + r1[lane];
        a1 += r0[lane + 32] + r1[lane + 32];
        a2 += r0[lane + 64] + r1[lane + 64];
    }
    if (e < s1) {
        const float* r = src + (size_t)colidx[e] * 96;
        a0 += r[lane]; a1 += r[lane + 32]; a2 += r[lane + 64];
    }
    float* dp = agg + (size_t)w * 96;
    dp[lane] = a0; dp[lane + 32] = a1; dp[lane + 64] = a2;
}

// ---------------- segment boundaries (sorted segment ids) ----------------
__global__ void k_bound(const int* __restrict__ seg, int n, int nseg,
                        int* __restrict__ start) {
    int i = blockIdx.x * blockDim.x + threadIdx.x;
    if (i == 0) { start[0] = 0; start[nseg] = n; }
    else if (i < n) {
        int c0 = seg[i - 1], c1 = seg[i];
        for (int c = c0 + 1; c <= c1; ++c) start[c] = i;
    }
}

// cluster pool: y[c][f] = BN2( segment-max over nodes of h2 ), sign-safe fold.
// thread 96 computes ybatch[c] = batch[last node] (batch sorted).
__global__ void __launch_bounds__(128)
k_pool(const float* __restrict__ h2, const int* __restrict__ nstart,
       const int* __restrict__ batch, const float* __restrict__ scale,
       const float* __restrict__ shift, float* __restrict__ y, int* __restrict__ ybatch) {
    int c = blockIdx.x;
    int t = threadIdx.x;
    int ns = nstart[c], ne = nstart[c + 1];
    if (t < 96) {
        float mx = -FLT_MAX, mn = FLT_MAX;
        for (int n = ns; n < ne; ++n) {
            float v = h2[(size_t)n * 96 + t];
            mx = fmaxf(mx, v); mn = fminf(mn, v);
        }
        float sc = scale[t];
        y[(size_t)c * 96 + t] = fmaf(sc >= 0.f ? mx : mn, sc, shift[t]);
    } else if (t == 96 && ne > ns) {
        ybatch[c] = batch[ne - 1];
    }
}

// final pool: out[g][f] = max over clusters of y2
__global__ void __launch_bounds__(256)
k_final(const float* __restrict__ y2, const int* __restrict__ gstart,
        float* __restrict__ out) {
    int g = blockIdx.x;
    int f = threadIdx.x;
    int gs = gstart[g], ge = gstart[g + 1];
    float mx = -FLT_MAX;
    for (int c = gs; c < ge; ++c)
        mx = fmaxf(mx, y2[(size_t)c * 256 + f]);
    out[(size_t)g * 256 + f] = mx;
}

// ---------------- embed ----------------
__global__ void k_embed(const int* __restrict__ x, const float* __restrict__ emb,
                        float* __restrict__ h0) {
    int i = blockIdx.x * blockDim.x + threadIdx.x;   // NN*16
    if (i < NN * 16) {
        int n = i >> 4, q = i & 15;
        reinterpret_cast<float4*>(h0)[i] =
            reinterpret_cast<const float4*>(emb)[x[n] * 16 + q];
    }
}

// ---------------- fused GEMM (+relu, +BN stats, optional BN-on-z-h-half) ----------------
template <int DAGG, int DH, int MTOT, int MCHUNK, bool STATS, bool BNZ>
__global__ void __launch_bounds__(256)
k_gemm(const float* __restrict__ agg, const float* __restrict__ h,
       const float* __restrict__ W, const float* __restrict__ bias,
       float* __restrict__ out, int N, double* __restrict__ stats,
       const float* __restrict__ zsc, const float* __restrict__ zsh) {
    constexpr int K   = DAGG + DH;
    constexpr int NK  = K / 32;
    constexpr int OPT = MCHUNK / 16;
    constexpr int ZS  = 66;
    static_assert(K % 32 == 0 && MCHUNK % 16 == 0, "tile shape");

    __shared__ float z_s[32 * ZS];
    __shared__ float w_s[32][MCHUNK + 2];

    const int t     = threadIdx.x;
    const int tn    = t & 15;
    const int tm    = t >> 4;
    const int nbase = blockIdx.x * 64;
    const int cbase = blockIdx.y * MCHUNK;

    u64t acc0[OPT], acc1[OPT];
#pragma unroll
    for (int j = 0; j < OPT; ++j) { acc0[j] = 0ull; acc1[j] = 0ull; }

    for (int c = 0; c < NK; ++c) {
#pragma unroll
        for (int r = 0; r < 8; ++r) {
            int idx = t + r * 256;           // 0..2047
            int kk = idx & 31, n = idx >> 5;
            int node = nbase + n;
            int k = c * 32 + kk;
            float v = 0.f;
            if (node < N) {
                if (k < DAGG) v = agg[(size_t)node * DAGG + k];
                else {
                    float hv = h[(size_t)node * DH + (k - DAGG)];
                    v = BNZ ? fmaf(hv, zsc[k - DAGG], zsh[k - DAGG]) : hv;
                }
            }
            z_s[kk * ZS + (n & 15) * 4 + (n >> 4)] = v;
        }
#pragma unroll
        for (int idx = t; idx < 32 * MCHUNK; idx += 256) {
            int kk = idx & 31, j = idx >> 5;
            w_s[kk][j] = W[(size_t)(cbase + j) * K + c * 32 + kk];
        }
        __syncthreads();

#pragma unroll 8
        for (int kk = 0; kk < 32; ++kk) {
            const float* zp = &z_s[kk * ZS + tn * 4];
            u64t z0 = *reinterpret_cast<const u64t*>(zp);
            u64t z1 = *reinterpret_cast<const u64t*>(zp + 2);
#pragma unroll
            for (int j = 0; j < OPT; ++j) {
                float wv = w_s[kk][tm * OPT + j];
                u64t wb = pk2(wv, wv);
                fma2(acc0[j], z0, wb);
                fma2(acc1[j], z1, wb);
            }
        }
        __syncthreads();
    }

#pragma unroll
    for (int j = 0; j < OPT; ++j) {
        int jg = cbase + tm * OPT + j;
        float bj = bias[jg];
        float v[4];
        upk2(v[0], v[1], acc0[j]);
        upk2(v[2], v[3], acc1[j]);
        float s = 0.f, s2 = 0.f;
#pragma unroll
        for (int i = 0; i < 4; ++i) {
            int node = nbase + tn + 16 * i;
            if (node < N) {
                float r = fmaxf(v[i] + bj, 0.f);
                out[(size_t)node * MTOT + jg] = r;
                s += r;
                s2 += r * r;
            }
        }
        if (STATS) {
#pragma unroll
            for (int off = 8; off; off >>= 1) {
                s  += __shfl_down_sync(0xffffffffu, s,  off, 16);
                s2 += __shfl_down_sync(0xffffffffu, s2, off, 16);
            }
            if (tn == 0) {
                atomicAdd(&stats[jg], (double)s);
                atomicAdd(&stats[256 + jg], (double)s2);
            }
        }
    }
}

// BN finalize
__global__ void k_bnfin(const double* __restrict__ stats, const float* __restrict__ g,
                        const float* __restrict__ be, float* __restrict__ scale,
                        float* __restrict__ shift, int M, int N) {
    int j = blockIdx.x * blockDim.x + threadIdx.x;
    if (j < M) {
        double inv = 1.0 / (double)N;
        float mean = (float)(stats[j] * inv);
        float var  = (float)(stats[256 + j] * inv) - mean * mean;
        float sc   = rsqrtf(var + EPSB) * g[j];
        scale[j] = sc;
        shift[j] = be[j] - mean * sc;
    }
}

// ---------------- launch ----------------
static inline int cdiv(int a, int b) { return (a + b - 1) / b; }

extern "C" void kernel_launch(void* const* d_in, const int* in_sizes, int n_in,
                              void* d_out, int out_size) {
    (void)in_sizes; (void)n_in; (void)out_size;
    const int*   x       = (const int*)d_in[0];
    const int*   ei      = (const int*)d_in[1];
    const int*   batch   = (const int*)d_in[2];
    const int*   cluster = (const int*)d_in[3];
    const int*   gei     = (const int*)d_in[4];
    const float* emb     = (const float*)d_in[5];
    const float* w1      = (const float*)d_in[6];
    const float* b1      = (const float*)d_in[7];
    const float* g1      = (const float*)d_in[8];
    const float* be1     = (const float*)d_in[9];
    const float* w2      = (const float*)d_in[10];
    const float* b2      = (const float*)d_in[11];
    const float* g2      = (const float*)d_in[12];
    const float* be2     = (const float*)d_in[13];
    const float* wm      = (const float*)d_in[14];
    const float* bm      = (const float*)d_in[15];
    float* out = (float*)d_out;

    float *h0, *agg, *h1, *h2, *y, *y2, *scale, *shift;
    int *cnt, *rowptr, *cur, *colidx, *growptr, *gcolidx;
    int *nstart, *gstart, *ybatch, *psum, *poff;
    double* stats;
    cudaGetSymbolAddress((void**)&h0,      g_h0);
    cudaGetSymbolAddress((void**)&agg,     g_agg);
    cudaGetSymbolAddress((void**)&h1,      g_h1);
    cudaGetSymbolAddress((void**)&h2,      g_h2);
    cudaGetSymbolAddress((void**)&y,       g_y);
    cudaGetSymbolAddress((void**)&y2,      g_y2);
    cudaGetSymbolAddress((void**)&cnt,     g_cnt);
    cudaGetSymbolAddress((void**)&rowptr,  g_rowptr);
    cudaGetSymbolAddress((void**)&cur,     g_cur);
    cudaGetSymbolAddress((void**)&colidx,  g_colidx);
    cudaGetSymbolAddress((void**)&growptr, g_growptr);
    cudaGetSymbolAddress((void**)&gcolidx, g_gcolidx);
    cudaGetSymbolAddress((void**)&nstart,  g_nstart);
    cudaGetSymbolAddress((void**)&gstart,  g_gstart);
    cudaGetSymbolAddress((void**)&ybatch,  g_ybatch);
    cudaGetSymbolAddress((void**)&psum,    g_psum);
    cudaGetSymbolAddress((void**)&poff,    g_poff);
    cudaGetSymbolAddress((void**)&stats,   g_stats);
    cudaGetSymbolAddress((void**)&scale,   g_scale);
    cudaGetSymbolAddress((void**)&shift,   g_shift);

    const int T = 256;

    // ---- node-level CSR (dst = ei[NE..2NE)) ----
    k_fill_i<<<cdiv(NN, T), T>>>(cnt, 0, NN);
    k_hist<<<cdiv(NE, T), T>>>(ei + NE, NE, cnt);
    k_scan1<<<cdiv(NN, 1024), 256>>>(cnt, rowptr, psum, NN);
    k_scan2<<<1, 128>>>(psum, poff, cdiv(NN, 1024));
    k_scan3<<<cdiv(NN, T), T>>>(rowptr, cur, poff, NN, NE);
    k_ticket<<<cdiv(NE, T), T>>>(ei, NE, cur, colidx);

    // ---- cluster-level CSR ----
    k_fill_i<<<cdiv(NC, T), T>>>(cnt, 0, NC);
    k_hist<<<cdiv(NGE, T), T>>>(gei + NGE, NGE, cnt);
    k_scan1<<<cdiv(NC, 1024), 256>>>(cnt, growptr, psum, NC);
    k_scan2<<<1, 128>>>(psum, poff, cdiv(NC, 1024));
    k_scan3<<<cdiv(NC, T), T>>>(growptr, cur, poff, NC, NGE);
    k_ticket<<<cdiv(NGE, T), T>>>(gei, NGE, cur, gcolidx);

    // ---- segment boundaries (sorted cluster ids) ----
    k_bound<<<cdiv(NN, T), T>>>(cluster, NN, NC, nstart);

    // ---- layer 1: conv(64 -> 80), stats ----
    k_fill_d<<<2, T>>>(stats, 512);
    k_embed<<<cdiv(NN * 16, T), T>>>(x, emb, h0);
    k_gather_emb<<<cdiv(NN * 32, T), T>>>(rowptr, colidx, x, emb, agg);
    k_gemm<64, 64, 80, 80, true, false><<<dim3(cdiv(NN, 64), 1), T>>>(
        agg, h0, w1, b1, h1, NN, stats, nullptr, nullptr);
    k_bnfin<<<1, 128>>>(stats, g1, be1, scale, shift, 80, NN);

    // ---- layer 2: conv(80 -> 96), BN1 folded into gather + z-load ----
    k_fill_d<<<2, T>>>(stats, 512);
    k_gather_bn80<<<cdiv(NN * 32, T), T>>>(rowptr, colidx, h1, scale, shift, agg);
    k_gemm<80, 80, 96, 96, true, true><<<dim3(cdiv(NN, 64), 1), T>>>(
        agg, h1, w2, b2, h2, NN, stats, scale, shift);
    k_bnfin<<<1, 128>>>(stats, g2, be2, scale + 96, shift + 96, 96, NN);

    // ---- cluster max-pool with BN2 fold (sign-safe) + ybatch ----
    k_pool<<<NC, 128>>>(h2, nstart, batch, scale + 96, shift + 96, y, ybatch);
    k_bound<<<cdiv(NC, T), T>>>(ybatch, NC, NG, gstart);

    // ---- global conv(96 -> 256) ----
    k_gather96<<<cdiv(NC * 32, T), T>>>(growptr, gcolidx, y, agg, NC);
    k_gemm<96, 96, 256, 128, false, false><<<dim3(cdiv(NC, 64), 2), T>>>(
        agg, y, wm, bm, y2, NC, nullptr, nullptr, nullptr);

    // ---- graph max-pool -> output ----
    k_final<<<NG, 256>>>(y2, gstart, out);
}

// round 5
// speedup vs baseline: 1.4095x; 1.0646x over previous
#include <cuda_runtime.h>
#include <cfloat>
#include <math.h>

// ---------------- problem constants ----------------
#define NN   100000   // nodes
#define NE   800000   // edges
#define NC   20000    // clusters
#define NGE  320000   // global edges
#define NG   256      // graphs
#define EPSB 1e-5f
#define NSEG (NN + NC)
#define NEALL (NE + NGE)
#define SLOT8 8
#define SQOFF (256 * SLOT8)         // sumsq offset within a layer region (doubles)
#define LSTRIDE (512 * SLOT8)       // doubles per layer region

// ---------------- scratch (device globals) ----------------
__device__ __align__(16) float  g_agg[NN * 96];
__device__ __align__(16) float  g_h1[NN * 80];
__device__ __align__(16) float  g_h2[NN * 96];
__device__ __align__(16) float  g_y [NC * 96];
__device__ __align__(16) float  g_y2[NC * 256];
__device__ __align__(16) int    g_cnt[NSEG];
__device__ __align__(16) int    g_rowptr[NSEG + 1];
__device__ __align__(16) int    g_cur[NSEG];
__device__ __align__(16) int    g_colidx[NEALL];
__device__ int    g_nstart[NC + 1];
__device__ int    g_gstart[NG + 1];
__device__ int    g_ybatch[NC];
__device__ int    g_psum[128];
__device__ int    g_poff[128];
__device__ double g_stats[2 * LSTRIDE];   // [layer][sum/sumsq][256][8]
__device__ float  g_scale[256];
__device__ float  g_shift[256];

// ---------------- packed f32x2 helpers ----------------
typedef unsigned long long u64t;
__device__ __forceinline__ u64t pk2(float lo, float hi) {
    u64t r; asm("mov.b64 %0, {%1, %2};" : "=l"(r) : "f"(lo), "f"(hi)); return r;
}
__device__ __forceinline__ void upk2(float& lo, float& hi, u64t v) {
    asm("mov.b64 {%0, %1}, %2;" : "=f"(lo), "=f"(hi) : "l"(v));
}
__device__ __forceinline__ void fma2(u64t& d, u64t a, u64t b) {
    asm("fma.rn.f32x2 %0, %1, %2, %0;" : "+l"(d) : "l"(a), "l"(b));
}

// ---------------- CSR build (combined node+cluster): hist -> scan -> ticket ----------------
__global__ void k_hist(const int* __restrict__ ei, const int* __restrict__ gei,
                       int* __restrict__ cnt) {
    int i = blockIdx.x * blockDim.x + threadIdx.x;
    if (i < NE) atomicAdd(&cnt[ei[NE + i]], 1);
    else if (i < NEALL) atomicAdd(&cnt[NN + gei[NGE + (i - NE)]], 1);
}

// per-1024-chunk exclusive scan (local), block sums to psum
__global__ void k_scan1(const int* __restrict__ cnt, int* __restrict__ loc,
                        int* __restrict__ psum, int n) {
    __shared__ int sh[256];
    int t = threadIdx.x;
    int idx = blockIdx.x * 1024 + t * 4;
    int a0 = 0, a1 = 0, a2 = 0, a3 = 0;
    if (idx + 3 < n) {
        int4 q = *reinterpret_cast<const int4*>(cnt + idx);
        a0 = q.x; a1 = q.y; a2 = q.z; a3 = q.w;
    } else {
        if (idx     < n) a0 = cnt[idx];
        if (idx + 1 < n) a1 = cnt[idx + 1];
        if (idx + 2 < n) a2 = cnt[idx + 2];
    }
    int s = a0 + a1 + a2 + a3;
    sh[t] = s; __syncthreads();
    for (int off = 1; off < 256; off <<= 1) {
        int u = (t >= off) ? sh[t - off] : 0;
        __syncthreads(); sh[t] += u; __syncthreads();
    }
    int excl = sh[t] - s;
    if (idx     < n) loc[idx]     = excl;
    if (idx + 1 < n) loc[idx + 1] = excl + a0;
    if (idx + 2 < n) loc[idx + 2] = excl + a0 + a1;
    if (idx + 3 < n) loc[idx + 3] = excl + a0 + a1 + a2;
    if (t == 255) psum[blockIdx.x] = sh[t];
}

__global__ void k_scan2(const int* __restrict__ psum, int* __restrict__ poff, int nb) {
    __shared__ int sh[128];
    int t = threadIdx.x;
    int v = (t < nb) ? psum[t] : 0;
    sh[t] = v; __syncthreads();
    for (int off = 1; off < 128; off <<= 1) {
        int u = (t >= off) ? sh[t - off] : 0;
        __syncthreads(); sh[t] += u; __syncthreads();
    }
    if (t < nb) poff[t] = sh[t] - v;
}

__global__ void k_scan3(int* __restrict__ rowptr, int* __restrict__ cur,
                        const int* __restrict__ poff, int n, int total) {
    int i = blockIdx.x * blockDim.x + threadIdx.x;
    if (i < n) {
        int v = rowptr[i] + poff[i >> 10];
        rowptr[i] = v;
        cur[i] = v;
    }
    if (i == 0) rowptr[n] = total;
}

__global__ void k_ticket(const int* __restrict__ ei, const int* __restrict__ gei,
                         int* __restrict__ cur, int* __restrict__ colidx) {
    int i = blockIdx.x * blockDim.x + threadIdx.x;
    if (i < NE) {
        int p = atomicAdd(&cur[ei[NE + i]], 1);
        colidx[p] = ei[i];
    } else if (i < NEALL) {
        int e = i - NE;
        int p = atomicAdd(&cur[NN + gei[NGE + e]], 1);
        colidx[p] = gei[e];
    }
}

// ---------------- gather aggregations (warp per node, register acc) ----------------
// agg1[n] = sum over in-edges of emb[x[src]]
__global__ void k_gather_emb(const int* __restrict__ rowptr, const int* __restrict__ colidx,
                             const int* __restrict__ x, const float* __restrict__ emb,
                             float* __restrict__ agg) {
    int w = (blockIdx.x * blockDim.x + threadIdx.x) >> 5;
    int lane = threadIdx.x & 31;
    if (w >= NN) return;
    int s0 = rowptr[w], s1 = rowptr[w + 1];
    float a0 = 0.f, a1 = 0.f;
    int e = s0;
    for (; e + 1 < s1; e += 2) {
        const float* r0 = emb + x[colidx[e]] * 64;
        const float* r1 = emb + x[colidx[e + 1]] * 64;
        a0 += r0[lane] + r1[lane];
        a1 += r0[lane + 32] + r1[lane + 32];
    }
    if (e < s1) {
        const float* r = emb + x[colidx[e]] * 64;
        a0 += r[lane]; a1 += r[lane + 32];
    }
    agg[(size_t)w * 64 + lane] = a0;
    agg[(size_t)w * 64 + lane + 32] = a1;
}

// agg2[n] = scale * (sum h1[src]) + deg * shift  (BN1 fold; D=80)
__global__ void k_gather_bn80(const int* __restrict__ rowptr, const int* __restrict__ colidx,
                              const float* __restrict__ h1, const float* __restrict__ scale,
                              const float* __restrict__ shift, float* __restrict__ agg) {
    int w = (blockIdx.x * blockDim.x + threadIdx.x) >> 5;
    int lane = threadIdx.x & 31;
    if (w >= NN) return;
    int s0 = rowptr[w], s1 = rowptr[w + 1];
    float a0 = 0.f, a1 = 0.f, a2 = 0.f;
    int e = s0;
    for (; e + 1 < s1; e += 2) {
        const float* r0 = h1 + (size_t)colidx[e] * 80;
        const float* r1 = h1 + (size_t)colidx[e + 1] * 80;
        a0 += r0[lane] + r1[lane];
        a1 += r0[lane + 32] + r1[lane + 32];
        if (lane < 16) a2 += r0[lane + 64] + r1[lane + 64];
    }
    if (e < s1) {
        const float* r = h1 + (size_t)colidx[e] * 80;
        a0 += r[lane]; a1 += r[lane + 32];
        if (lane < 16) a2 += r[lane + 64];
    }
    float deg = (float)(s1 - s0);
    float* dp = agg + (size_t)w * 80;
    dp[lane]      = fmaf(a0, scale[lane],      deg * shift[lane]);
    dp[lane + 32] = fmaf(a1, scale[lane + 32], deg * shift[lane + 32]);
    if (lane < 16)
        dp[lane + 64] = fmaf(a2, scale[lane + 64], deg * shift[lane + 64]);
}

// agg3[c] = sum y[src]  (D=96); rowptr/colidx at combined offsets
__global__ void k_gather96(const int* __restrict__ rowptr, const int* __restrict__ colidx,
                           const float* __restrict__ src, float* __restrict__ agg, int N) {
    int w = (blockIdx.x * blockDim.x + threadIdx.x) >> 5;
    int lane = threadIdx.x & 31;
    if (w >= N) return;
    int s0 = rowptr[w], s1 = rowptr[w + 1];
    float a0 = 0.f, a1 = 0.f, a2 = 0.f;
    int e = s0;
    for (; e + 1 < s1; e += 2) {
        const float* r0 = src + (size_t)colidx[e] * 96;
        const float* r1 = src + (size_t)colidx[e + 1] * 96;
        a0 += r0[lane] + r1[lane];
        a1 += r0[lane + 32] + r1[lane + 32];
        a2 += r0[lane + 64] + r1[lane + 64];
    }
    if (e < s1) {
        const float* r = src + (size_t)colidx[e] * 96;
        a0 += r[lane]; a1 += r[lane + 32]; a2 += r[lane + 64];
    }
    float* dp = agg + (size_t)w * 96;
    dp[lane] = a0; dp[lane + 32] = a1; dp[lane + 64] = a2;
}

// ---------------- segment boundaries (sorted segment ids) ----------------
__global__ void k_bound(const int* __restrict__ seg, int n, int nseg,
                        int* __restrict__ start) {
    int i = blockIdx.x * blockDim.x + threadIdx.x;
    if (i == 0) { start[0] = 0; start[nseg] = n; }
    else if (i < n) {
        int c0 = seg[i - 1], c1 = seg[i];
        for (int c = c0 + 1; c <= c1; ++c) start[c] = i;
    }
}

// cluster pool: y[c][f] = BN2( segment-max over nodes of h2 ), sign-safe fold.
__global__ void __launch_bounds__(128)
k_pool(const float* __restrict__ h2, const int* __restrict__ nstart,
       const int* __restrict__ batch, const float* __restrict__ scale,
       const float* __restrict__ shift, float* __restrict__ y, int* __restrict__ ybatch) {
    int c = blockIdx.x;
    int t = threadIdx.x;
    int ns = nstart[c], ne = nstart[c + 1];
    if (t < 96) {
        float mx = -FLT_MAX, mn = FLT_MAX;
        for (int n = ns; n < ne; ++n) {
            float v = h2[(size_t)n * 96 + t];
            mx = fmaxf(mx, v); mn = fminf(mn, v);
        }
        float sc = scale[t];
        y[(size_t)c * 96 + t] = fmaf(sc >= 0.f ? mx : mn, sc, shift[t]);
    } else if (t == 96 && ne > ns) {
        ybatch[c] = batch[ne - 1];
    }
}

// final pool: out[g][f] = max over clusters of y2
__global__ void __launch_bounds__(256)
k_final(const float* __restrict__ y2, const int* __restrict__ gstart,
        float* __restrict__ out) {
    int g = blockIdx.x;
    int f = threadIdx.x;
    int gs = gstart[g], ge = gstart[g + 1];
    float mx = -FLT_MAX;
    for (int c = gs; c < ge; ++c)
        mx = fmaxf(mx, y2[(size_t)c * 256 + f]);
    out[(size_t)g * 256 + f] = mx;
}

// ---------------- fused GEMM (+relu, +stats; h-half = emb[x[n]] or BN(h)) ----------------
// out[N, MTOT] (cols [cbase..)) = relu( [agg | h] @ W^T + bias )
// W staged in smem as duplicated f32x2 pairs -> no pack in the inner loop.
template <int DAGG, int DH, int MTOT, int MCHUNK, bool STATS, bool BNZ, bool EMB>
__global__ void __launch_bounds__(256)
k_gemm(const float* __restrict__ agg, const float* __restrict__ h,
       const int* __restrict__ x, const float* __restrict__ emb,
       const float* __restrict__ W, const float* __restrict__ bias,
       float* __restrict__ out, int N, double* __restrict__ stats,
       const float* __restrict__ zsc, const float* __restrict__ zsh) {
    constexpr int K   = DAGG + DH;
    constexpr int NK  = K / 32;
    constexpr int OPT = MCHUNK / 16;
    constexpr int ZS  = 66;
    static_assert(K % 32 == 0 && MCHUNK % 16 == 0, "tile shape");

    __shared__ float z_s[32 * ZS];
    __shared__ u64t  w_s[MCHUNK * 32];    // [j][kk], duplicated pairs

    const int t     = threadIdx.x;
    const int tn    = t & 15;
    const int tm    = t >> 4;
    const int nbase = blockIdx.x * 64;
    const int cbase = blockIdx.y * MCHUNK;

    u64t acc0[OPT], acc1[OPT];
#pragma unroll
    for (int j = 0; j < OPT; ++j) { acc0[j] = 0ull; acc1[j] = 0ull; }

    for (int c = 0; c < NK; ++c) {
        // z tile: value for (node nbase+n, k=c*32+kk) at z_s[kk*ZS + (n&15)*4 + (n>>4)]
#pragma unroll
        for (int r = 0; r < 8; ++r) {
            int idx = t + r * 256;           // 0..2047
            int kk = idx & 31, n = idx >> 5;
            int node = nbase + n;
            int k = c * 32 + kk;
            float v = 0.f;
            if (node < N) {
                if (k < DAGG) v = agg[(size_t)node * DAGG + k];
                else if (EMB) v = emb[x[node] * DH + (k - DAGG)];
                else {
                    float hv = h[(size_t)node * DH + (k - DAGG)];
                    v = BNZ ? fmaf(hv, zsc[k - DAGG], zsh[k - DAGG]) : hv;
                }
            }
            z_s[kk * ZS + (n & 15) * 4 + (n >> 4)] = v;
        }
        // W tile: duplicated pairs, [j][kk] (coalesced STS.64)
#pragma unroll
        for (int idx = t; idx < 32 * MCHUNK; idx += 256) {
            int kk = idx & 31, j = idx >> 5;
            float wv = W[(size_t)(cbase + j) * K + c * 32 + kk];
            w_s[j * 32 + kk] = pk2(wv, wv);
        }
        __syncthreads();

#pragma unroll 8
        for (int kk = 0; kk < 32; ++kk) {
            const float* zp = &z_s[kk * ZS + tn * 4];
            u64t z0 = *reinterpret_cast<const u64t*>(zp);       // nodes tn, tn+16
            u64t z1 = *reinterpret_cast<const u64t*>(zp + 2);   // nodes tn+32, tn+48
            const u64t* wp = &w_s[(tm * OPT) * 32 + kk];
#pragma unroll
            for (int j = 0; j < OPT; ++j) {
                u64t wb = wp[j * 32];
                fma2(acc0[j], z0, wb);
                fma2(acc1[j], z1, wb);
            }
        }
        __syncthreads();
    }

    // epilogue: bias + relu + store + (optional) 8-slot-decontended stats
    int slot = blockIdx.x & (SLOT8 - 1);
#pragma unroll
    for (int j = 0; j < OPT; ++j) {
        int jg = cbase + tm * OPT + j;
        float bj = bias[jg];
        float v[4];
        upk2(v[0], v[1], acc0[j]);
        upk2(v[2], v[3], acc1[j]);
        float s = 0.f, s2 = 0.f;
#pragma unroll
        for (int i = 0; i < 4; ++i) {
            int node = nbase + tn + 16 * i;
            if (node < N) {
                float r = fmaxf(v[i] + bj, 0.f);
                out[(size_t)node * MTOT + jg] = r;
                s += r;
                s2 += r * r;
            }
        }
        if (STATS) {
#pragma unroll
            for (int off = 8; off; off >>= 1) {
                s  += __shfl_down_sync(0xffffffffu, s,  off, 16);
                s2 += __shfl_down_sync(0xffffffffu, s2, off, 16);
            }
            if (tn == 0) {
                atomicAdd(&stats[jg * SLOT8 + slot], (double)s);
                atomicAdd(&stats[SQOFF + jg * SLOT8 + slot], (double)s2);
            }
        }
    }
}

// BN finalize: reduce 8 slots, biased variance
__global__ void k_bnfin(const double* __restrict__ stats, const float* __restrict__ g,
                        const float* __restrict__ be, float* __restrict__ scale,
                        float* __restrict__ shift, int M, int N) {
    int j = blockIdx.x * blockDim.x + threadIdx.x;
    if (j < M) {
        double s = 0.0, s2 = 0.0;
#pragma unroll
        for (int k = 0; k < SLOT8; ++k) {
            s  += stats[j * SLOT8 + k];
            s2 += stats[SQOFF + j * SLOT8 + k];
        }
        double inv = 1.0 / (double)N;
        float mean = (float)(s * inv);
        float var  = (float)(s2 * inv) - mean * mean;
        float sc   = rsqrtf(var + EPSB) * g[j];
        scale[j] = sc;
        shift[j] = be[j] - mean * sc;
    }
}

// ---------------- launch ----------------
static inline int cdiv(int a, int b) { return (a + b - 1) / b; }

extern "C" void kernel_launch(void* const* d_in, const int* in_sizes, int n_in,
                              void* d_out, int out_size) {
    (void)in_sizes; (void)n_in; (void)out_size;
    const int*   x       = (const int*)d_in[0];
    const int*   ei      = (const int*)d_in[1];
    const int*   batch   = (const int*)d_in[2];
    const int*   cluster = (const int*)d_in[3];
    const int*   gei     = (const int*)d_in[4];
    const float* emb     = (const float*)d_in[5];
    const float* w1      = (const float*)d_in[6];
    const float* b1      = (const float*)d_in[7];
    const float* g1      = (const float*)d_in[8];
    const float* be1     = (const float*)d_in[9];
    const float* w2      = (const float*)d_in[10];
    const float* b2      = (const float*)d_in[11];
    const float* g2      = (const float*)d_in[12];
    const float* be2     = (const float*)d_in[13];
    const float* wm      = (const float*)d_in[14];
    const float* bm      = (const float*)d_in[15];
    float* out = (float*)d_out;

    float *agg, *h1, *h2, *y, *y2, *scale, *shift;
    int *cnt, *rowptr, *cur, *colidx;
    int *nstart, *gstart, *ybatch, *psum, *poff;
    double* stats;
    cudaGetSymbolAddress((void**)&agg,     g_agg);
    cudaGetSymbolAddress((void**)&h1,      g_h1);
    cudaGetSymbolAddress((void**)&h2,      g_h2);
    cudaGetSymbolAddress((void**)&y,       g_y);
    cudaGetSymbolAddress((void**)&y2,      g_y2);
    cudaGetSymbolAddress((void**)&cnt,     g_cnt);
    cudaGetSymbolAddress((void**)&rowptr,  g_rowptr);
    cudaGetSymbolAddress((void**)&cur,     g_cur);
    cudaGetSymbolAddress((void**)&colidx,  g_colidx);
    cudaGetSymbolAddress((void**)&nstart,  g_nstart);
    cudaGetSymbolAddress((void**)&gstart,  g_gstart);
    cudaGetSymbolAddress((void**)&ybatch,  g_ybatch);
    cudaGetSymbolAddress((void**)&psum,    g_psum);
    cudaGetSymbolAddress((void**)&poff,    g_poff);
    cudaGetSymbolAddress((void**)&stats,   g_stats);
    cudaGetSymbolAddress((void**)&scale,   g_scale);
    cudaGetSymbolAddress((void**)&shift,   g_shift);

    const int T = 256;

    // ---- zero counters + stats (async memsets, capturable) ----
    cudaMemsetAsync(cnt, 0, NSEG * sizeof(int));
    cudaMemsetAsync(stats, 0, 2 * LSTRIDE * sizeof(double));

    // ---- combined CSR build (nodes + clusters) ----
    k_hist<<<cdiv(NEALL, T), T>>>(ei, gei, cnt);
    k_scan1<<<cdiv(NSEG, 1024), 256>>>(cnt, rowptr, psum, NSEG);
    k_scan2<<<1, 128>>>(psum, poff, cdiv(NSEG, 1024));
    k_scan3<<<cdiv(NSEG, T), T>>>(rowptr, cur, poff, NSEG, NEALL);
    k_ticket<<<cdiv(NEALL, T), T>>>(ei, gei, cur, colidx);

    // ---- segment boundaries (sorted cluster ids) ----
    k_bound<<<cdiv(NN, T), T>>>(cluster, NN, NC, nstart);

    // ---- layer 1: conv(64 -> 80); h-half read directly from emb[x[n]] ----
    k_gather_emb<<<cdiv(NN * 32, T), T>>>(rowptr, colidx, x, emb, agg);
    k_gemm<64, 64, 80, 80, true, false, true><<<dim3(cdiv(NN, 64), 1), T>>>(
        agg, nullptr, x, emb, w1, b1, h1, NN, stats, nullptr, nullptr);
    k_bnfin<<<1, 128>>>(stats, g1, be1, scale, shift, 80, NN);

    // ---- layer 2: conv(80 -> 96), BN1 folded into gather + z-load ----
    k_gather_bn80<<<cdiv(NN * 32, T), T>>>(rowptr, colidx, h1, scale, shift, agg);
    k_gemm<80, 80, 96, 96, true, true, false><<<dim3(cdiv(NN, 64), 1), T>>>(
        agg, h1, nullptr, nullptr, w2, b2, h2, NN, stats + LSTRIDE, scale, shift);
    k_bnfin<<<1, 128>>>(stats + LSTRIDE, g2, be2, scale + 96, shift + 96, 96, NN);

    // ---- cluster max-pool with BN2 fold (sign-safe) + ybatch ----
    k_pool<<<NC, 128>>>(h2, nstart, batch, scale + 96, shift + 96, y, ybatch);
    k_bound<<<cdiv(NC, T), T>>>(ybatch, NC, NG, gstart);

    // ---- global conv(96 -> 256): cluster CSR lives at combined offset NN ----
    k_gather96<<<cdiv(NC * 32, T), T>>>(rowptr + NN, colidx, y, agg, NC);
    k_gemm<96, 96, 256, 128, false, false, false><<<dim3(cdiv(NC, 64), 2), T>>>(
        agg, y, nullptr, nullptr, wm, bm, y2, NC, nullptr, nullptr, nullptr);

    // ---- graph max-pool -> output ----
    k_final<<<NG, 256>>>(y2, gstart, out);
}

// round 6
// speedup vs baseline: 1.8060x; 1.2812x over previous
#include <cuda_runtime.h>
#include <cfloat>
#include <math.h>

// ---------------- problem constants ----------------
#define NN   100000   // nodes
#define NE   800000   // edges
#define NC   20000    // clusters
#define NGE  320000   // global edges
#define NG   256      // graphs
#define EPSB 1e-5f
#define NSEG (NN + NC)
#define NEALL (NE + NGE)
#define SLOT8 8
#define SQOFF (256 * SLOT8)         // sumsq offset within a layer region (doubles)
#define LSTRIDE (512 * SLOT8)       // doubles per layer region
#define CNT_BYTES (NSEG * 4)        // 480000, 16B-aligned
#define ZERO_BYTES (CNT_BYTES + 2 * LSTRIDE * 8)

// ---------------- scratch (device globals) ----------------
__device__ __align__(16) float  g_agg[NN * 96];
__device__ __align__(16) float  g_h1[NN * 80];
__device__ __align__(16) float  g_h2[NN * 96];
__device__ __align__(16) float  g_y [NC * 96];
__device__ __align__(16) float  g_y2[NC * 256];
__device__ __align__(16) unsigned char g_zerobuf[ZERO_BYTES];   // [cnt | stats]
__device__ __align__(16) int    g_rowptr[NSEG + 1];
__device__ __align__(16) int    g_cur[NSEG];
__device__ __align__(16) int    g_colidx[NEALL];
__device__ int    g_nstart[NC + 1];
__device__ int    g_gstart[NG + 1];
__device__ int    g_ybatch[NC];
__device__ int    g_psum[128];
__device__ int    g_poff[128];
__device__ float  g_scale[256];
__device__ float  g_shift[256];

// ---------------- tf32 / mma helpers ----------------
__device__ __forceinline__ unsigned tf32cvt(float f) {
    unsigned u;
    asm("cvt.rna.tf32.f32 %0, %1;" : "=r"(u) : "f"(f));
    return u;
}
__device__ __forceinline__ void mma_tf32(float4& d, uint2 a01, uint2 a23, uint2 b) {
    asm volatile(
        "mma.sync.aligned.m16n8k8.row.col.f32.tf32.tf32.f32 "
        "{%0,%1,%2,%3}, {%4,%5,%6,%7}, {%8,%9}, {%0,%1,%2,%3};"
        : "+f"(d.x), "+f"(d.y), "+f"(d.z), "+f"(d.w)
        : "r"(a01.x), "r"(a01.y), "r"(a23.x), "r"(a23.y), "r"(b.x), "r"(b.y));
}

// ---------------- CSR build (combined node+cluster): hist -> scan -> ticket ----------------
__global__ void k_hist(const int* __restrict__ ei, const int* __restrict__ gei,
                       int* __restrict__ cnt) {
    int i = blockIdx.x * blockDim.x + threadIdx.x;
    if (i < NE) atomicAdd(&cnt[ei[NE + i]], 1);
    else if (i < NEALL) atomicAdd(&cnt[NN + gei[NGE + (i - NE)]], 1);
}

__global__ void k_scan1(const int* __restrict__ cnt, int* __restrict__ loc,
                        int* __restrict__ psum, int n) {
    __shared__ int sh[256];
    int t = threadIdx.x;
    int idx = blockIdx.x * 1024 + t * 4;
    int a0 = 0, a1 = 0, a2 = 0, a3 = 0;
    if (idx + 3 < n) {
        int4 q = *reinterpret_cast<const int4*>(cnt + idx);
        a0 = q.x; a1 = q.y; a2 = q.z; a3 = q.w;
    } else {
        if (idx     < n) a0 = cnt[idx];
        if (idx + 1 < n) a1 = cnt[idx + 1];
        if (idx + 2 < n) a2 = cnt[idx + 2];
    }
    int s = a0 + a1 + a2 + a3;
    sh[t] = s; __syncthreads();
    for (int off = 1; off < 256; off <<= 1) {
        int u = (t >= off) ? sh[t - off] : 0;
        __syncthreads(); sh[t] += u; __syncthreads();
    }
    int excl = sh[t] - s;
    if (idx     < n) loc[idx]     = excl;
    if (idx + 1 < n) loc[idx + 1] = excl + a0;
    if (idx + 2 < n) loc[idx + 2] = excl + a0 + a1;
    if (idx + 3 < n) loc[idx + 3] = excl + a0 + a1 + a2;
    if (t == 255) psum[blockIdx.x] = sh[t];
}

__global__ void k_scan2(const int* __restrict__ psum, int* __restrict__ poff, int nb) {
    __shared__ int sh[128];
    int t = threadIdx.x;
    int v = (t < nb) ? psum[t] : 0;
    sh[t] = v; __syncthreads();
    for (int off = 1; off < 128; off <<= 1) {
        int u = (t >= off) ? sh[t - off] : 0;
        __syncthreads(); sh[t] += u; __syncthreads();
    }
    if (t < nb) poff[t] = sh[t] - v;
}

__global__ void k_scan3(int* __restrict__ rowptr, int* __restrict__ cur,
                        const int* __restrict__ poff, int n, int total) {
    int i = blockIdx.x * blockDim.x + threadIdx.x;
    if (i < n) {
        int v = rowptr[i] + poff[i >> 10];
        rowptr[i] = v;
        cur[i] = v;
    }
    if (i == 0) rowptr[n] = total;
}

__global__ void k_ticket(const int* __restrict__ ei, const int* __restrict__ gei,
                         int* __restrict__ cur, int* __restrict__ colidx) {
    int i = blockIdx.x * blockDim.x + threadIdx.x;
    if (i < NE) {
        int p = atomicAdd(&cur[ei[NE + i]], 1);
        colidx[p] = ei[i];
    } else if (i < NEALL) {
        int e = i - NE;
        int p = atomicAdd(&cur[NN + gei[NGE + e]], 1);
        colidx[p] = gei[e];
    }
}

// ---------------- gather aggregations (warp per node, register acc) ----------------
__global__ void k_gather_emb(const int* __restrict__ rowptr, const int* __restrict__ colidx,
                             const int* __restrict__ x, const float* __restrict__ emb,
                             float* __restrict__ agg) {
    int w = (blockIdx.x * blockDim.x + threadIdx.x) >> 5;
    int lane = threadIdx.x & 31;
    if (w >= NN) return;
    int s0 = rowptr[w], s1 = rowptr[w + 1];
    float a0 = 0.f, a1 = 0.f;
    int e = s0;
    for (; e + 1 < s1; e += 2) {
        const float* r0 = emb + x[colidx[e]] * 64;
        const float* r1 = emb + x[colidx[e + 1]] * 64;
        a0 += r0[lane] + r1[lane];
        a1 += r0[lane + 32] + r1[lane + 32];
    }
    if (e < s1) {
        const float* r = emb + x[colidx[e]] * 64;
        a0 += r[lane]; a1 += r[lane + 32];
    }
    agg[(size_t)w * 64 + lane] = a0;
    agg[(size_t)w * 64 + lane + 32] = a1;
}

__global__ void k_gather_bn80(const int* __restrict__ rowptr, const int* __restrict__ colidx,
                              const float* __restrict__ h1, const float* __restrict__ scale,
                              const float* __restrict__ shift, float* __restrict__ agg) {
    int w = (blockIdx.x * blockDim.x + threadIdx.x) >> 5;
    int lane = threadIdx.x & 31;
    if (w >= NN) return;
    int s0 = rowptr[w], s1 = rowptr[w + 1];
    float a0 = 0.f, a1 = 0.f, a2 = 0.f;
    int e = s0;
    for (; e + 1 < s1; e += 2) {
        const float* r0 = h1 + (size_t)colidx[e] * 80;
        const float* r1 = h1 + (size_t)colidx[e + 1] * 80;
        a0 += r0[lane] + r1[lane];
        a1 += r0[lane + 32] + r1[lane + 32];
        if (lane < 16) a2 += r0[lane + 64] + r1[lane + 64];
    }
    if (e < s1) {
        const float* r = h1 + (size_t)colidx[e] * 80;
        a0 += r[lane]; a1 += r[lane + 32];
        if (lane < 16) a2 += r[lane + 64];
    }
    float deg = (float)(s1 - s0);
    float* dp = agg + (size_t)w * 80;
    dp[lane]      = fmaf(a0, scale[lane],      deg * shift[lane]);
    dp[lane + 32] = fmaf(a1, scale[lane + 32], deg * shift[lane + 32]);
    if (lane < 16)
        dp[lane + 64] = fmaf(a2, scale[lane + 64], deg * shift[lane + 64]);
}

__global__ void k_gather96(const int* __restrict__ rowptr, const int* __restrict__ colidx,
                           const float* __restrict__ src, float* __restrict__ agg, int N) {
    int w = (blockIdx.x * blockDim.x + threadIdx.x) >> 5;
    int lane = threadIdx.x & 31;
    if (w >= N) return;
    int s0 = rowptr[w], s1 = rowptr[w + 1];
    float a0 = 0.f, a1 = 0.f, a2 = 0.f;
    int e = s0;
    for (; e + 1 < s1; e += 2) {
        const float* r0 = src + (size_t)colidx[e] * 96;
        const float* r1 = src + (size_t)colidx[e + 1] * 96;
        a0 += r0[lane] + r1[lane];
        a1 += r0[lane + 32] + r1[lane + 32];
        a2 += r0[lane + 64] + r1[lane + 64];
    }
    if (e < s1) {
        const float* r = src + (size_t)colidx[e] * 96;
        a0 += r[lane]; a1 += r[lane + 32]; a2 += r[lane + 64];
    }
    float* dp = agg + (size_t)w * 96;
    dp[lane] = a0; dp[lane + 32] = a1; dp[lane + 64] = a2;
}

// ---------------- segment boundaries (sorted segment ids) ----------------
__global__ void k_bound(const int* __restrict__ seg, int n, int nseg,
                        int* __restrict__ start) {
    int i = blockIdx.x * blockDim.x + threadIdx.x;
    if (i == 0) { start[0] = 0; start[nseg] = n; }
    else if (i < n) {
        int c0 = seg[i - 1], c1 = seg[i];
        for (int c = c0 + 1; c <= c1; ++c) start[c] = i;
    }
}

// cluster pool: y[c][f] = BN2( segment-max over nodes of h2 ), sign-safe fold.
__global__ void __launch_bounds__(128)
k_pool(const float* __restrict__ h2, const int* __restrict__ nstart,
       const int* __restrict__ batch, const float* __restrict__ scale,
       const float* __restrict__ shift, float* __restrict__ y, int* __restrict__ ybatch) {
    int c = blockIdx.x;
    int t = threadIdx.x;
    int ns = nstart[c], ne = nstart[c + 1];
    if (t < 96) {
        float mx = -FLT_MAX, mn = FLT_MAX;
        for (int n = ns; n < ne; ++n) {
            float v = h2[(size_t)n * 96 + t];
            mx = fmaxf(mx, v); mn = fminf(mn, v);
        }
        float sc = scale[t];
        y[(size_t)c * 96 + t] = fmaf(sc >= 0.f ? mx : mn, sc, shift[t]);
    } else if (t == 96 && ne > ns) {
        ybatch[c] = batch[ne - 1];
    }
}

// final pool: out[g][f] = max over clusters of y2
__global__ void __launch_bounds__(256)
k_final(const float* __restrict__ y2, const int* __restrict__ gstart,
        float* __restrict__ out) {
    int g = blockIdx.x;
    int f = threadIdx.x;
    int gs = gstart[g], ge = gstart[g + 1];
    float mx = -FLT_MAX;
    for (int c = gs; c < ge; ++c)
        mx = fmaxf(mx, y2[(size_t)c * 256 + f]);
    out[(size_t)g * 256 + f] = mx;
}

// ---------------- TF32 tensor-core GEMM (+relu, +BN stats) ----------------
// out[N, MTOT] (cols [cbase..cbase+MCHUNK)) = relu( [agg | h] @ W^T + bias )
// Block tile: 128 nodes x MCHUNK outs; 8 warps = 4 (node dim) x 2 (out dim).
// K chunked by 32. Z staged tf32 in smem node-pair-interleaved; W staged tf32
// k-interleaved so mma fragments are LDS.64 loads.
template <int K, int DAGG, int DH, int MTOT, int MCHUNK, bool STATS, bool BNZ, bool EMB>
__global__ void __launch_bounds__(256)
k_gemm_tc(const float* __restrict__ agg, const float* __restrict__ h,
          const int* __restrict__ x, const float* __restrict__ emb,
          const float* __restrict__ W, const float* __restrict__ bias,
          float* __restrict__ out, int N, double* __restrict__ stats,
          const float* __restrict__ zsc, const float* __restrict__ zsh) {
    constexpr int NK    = K / 32;
    constexpr int NSPAN = MCHUNK / 2;     // per-warp out span
    constexpr int NT    = NSPAN / 8;      // n-tiles per warp
    constexpr int ZS    = 136;            // z row stride (uints), even -> 8B aligned
    constexpr int WS    = 40;             // w row stride (uints)
    static_assert(K % 32 == 0 && MCHUNK % 16 == 0, "tile shape");

    __shared__ unsigned z_s[32 * ZS];         // [kk][node'] tf32
    __shared__ unsigned w_s[MCHUNK * WS];     // [j][k'] tf32

    const int t     = threadIdx.x;
    const int lane  = t & 31;
    const int wid   = t >> 5;
    const int wm    = wid & 3;            // warp row (32 nodes)
    const int wn    = wid >> 2;           // warp col (NSPAN outs)
    const int gr    = lane >> 2;
    const int tc    = lane & 3;
    const int nbase = blockIdx.x * 128;
    const int cbase = blockIdx.y * MCHUNK;

    float4 acc[2][NT];
#pragma unroll
    for (int mt = 0; mt < 2; ++mt)
#pragma unroll
        for (int nt = 0; nt < NT; ++nt) acc[mt][nt] = make_float4(0.f, 0.f, 0.f, 0.f);

    for (int c = 0; c < NK; ++c) {
        // ---- Z tile: (node nbase+n, k=c*32+kk) -> z_s[kk][perm(n)] ----
#pragma unroll
        for (int r = 0; r < 16; ++r) {
            int idx = t + r * 256;            // 0..4095
            int kk = idx & 31, n = idx >> 5;
            int node = nbase + n;
            int k = c * 32 + kk;
            float v = 0.f;
            if (node < N) {
                if (k < DAGG) v = agg[(size_t)node * DAGG + k];
                else if (EMB) v = emb[x[node] * DH + (k - DAGG)];
                else {
                    float hv = h[(size_t)node * DH + (k - DAGG)];
                    v = BNZ ? fmaf(hv, zsc[k - DAGG], zsh[k - DAGG]) : hv;
                }
            }
            int np = (n & 0x70) | ((n & 7) << 1) | ((n >> 3) & 1);
            z_s[kk * ZS + np] = tf32cvt(v);
        }
        // ---- W tile: W[cbase+j][c*32+kk] -> w_s[j][kperm] ----
#pragma unroll
        for (int idx = t; idx < 32 * MCHUNK; idx += 256) {
            int kk = idx & 31, j = idx >> 5;
            float wv = W[(size_t)(cbase + j) * K + c * 32 + kk];
            int kp = (kk & ~7) | ((kk & 3) << 1) | ((kk & 4) >> 2);
            w_s[j * WS + kp] = tf32cvt(wv);
        }
        __syncthreads();

#pragma unroll
        for (int g = 0; g < 4; ++g) {
            uint2 a01[2], a23[2];
#pragma unroll
            for (int mt = 0; mt < 2; ++mt) {
                int col = wm * 32 + mt * 16 + 2 * gr;
                a01[mt] = *reinterpret_cast<const uint2*>(&z_s[(g * 8 + tc) * ZS + col]);
                a23[mt] = *reinterpret_cast<const uint2*>(&z_s[(g * 8 + tc + 4) * ZS + col]);
            }
#pragma unroll
            for (int nt = 0; nt < NT; ++nt) {
                uint2 b = *reinterpret_cast<const uint2*>(
                    &w_s[(wn * NSPAN + nt * 8 + gr) * WS + g * 8 + tc * 2]);
                mma_tf32(acc[0][nt], a01[0], a23[0], b);
                mma_tf32(acc[1][nt], a01[1], a23[1], b);
            }
        }
        __syncthreads();
    }

    // ---- epilogue: bias + relu + store + BN stats ----
    const int slot = blockIdx.x & (SLOT8 - 1);
#pragma unroll
    for (int nt = 0; nt < NT; ++nt) {
        int col = cbase + wn * NSPAN + nt * 8 + 2 * tc;
        float b0 = bias[col], b1 = bias[col + 1];
        float s0 = 0.f, s1 = 0.f, q0 = 0.f, q1 = 0.f;
#pragma unroll
        for (int mt = 0; mt < 2; ++mt) {
            int node0 = nbase + wm * 32 + mt * 16 + gr;
            int node1 = node0 + 8;
            float4 a = acc[mt][nt];
            float r00 = fmaxf(a.x + b0, 0.f);
            float r01 = fmaxf(a.y + b1, 0.f);
            float r10 = fmaxf(a.z + b0, 0.f);
            float r11 = fmaxf(a.w + b1, 0.f);
            if (node0 < N) {
                *reinterpret_cast<float2*>(&out[(size_t)node0 * MTOT + col]) =
                    make_float2(r00, r01);
                s0 += r00; q0 += r00 * r00;
                s1 += r01; q1 += r01 * r01;
            }
            if (node1 < N) {
                *reinterpret_cast<float2*>(&out[(size_t)node1 * MTOT + col]) =
                    make_float2(r10, r11);
                s0 += r10; q0 += r10 * r10;
                s1 += r11; q1 += r11 * r11;
            }
        }
        if (STATS) {
#pragma unroll
            for (int off = 4; off < 32; off <<= 1) {
                s0 += __shfl_xor_sync(0xffffffffu, s0, off);
                s1 += __shfl_xor_sync(0xffffffffu, s1, off);
                q0 += __shfl_xor_sync(0xffffffffu, q0, off);
                q1 += __shfl_xor_sync(0xffffffffu, q1, off);
            }
            if (gr == 0) {
                atomicAdd(&stats[col * SLOT8 + slot], (double)s0);
                atomicAdd(&stats[(col + 1) * SLOT8 + slot], (double)s1);
                atomicAdd(&stats[SQOFF + col * SLOT8 + slot], (double)q0);
                atomicAdd(&stats[SQOFF + (col + 1) * SLOT8 + slot], (double)q1);
            }
        }
    }
}

// BN finalize: reduce 8 slots, biased variance
__global__ void k_bnfin(const double* __restrict__ stats, const float* __restrict__ g,
                        const float* __restrict__ be, float* __restrict__ scale,
                        float* __restrict__ shift, int M, int N) {
    int j = blockIdx.x * blockDim.x + threadIdx.x;
    if (j < M) {
        double s = 0.0, s2 = 0.0;
#pragma unroll
        for (int k = 0; k < SLOT8; ++k) {
            s  += stats[j * SLOT8 + k];
            s2 += stats[SQOFF + j * SLOT8 + k];
        }
        double inv = 1.0 / (double)N;
        float mean = (float)(s * inv);
        float var  = (float)(s2 * inv) - mean * mean;
        float sc   = rsqrtf(var + EPSB) * g[j];
        scale[j] = sc;
        shift[j] = be[j] - mean * sc;
    }
}

// ---------------- launch ----------------
static inline int cdiv(int a, int b) { return (a + b - 1) / b; }

extern "C" void kernel_launch(void* const* d_in, const int* in_sizes, int n_in,
                              void* d_out, int out_size) {
    (void)in_sizes; (void)n_in; (void)out_size;
    const int*   x       = (const int*)d_in[0];
    const int*   ei      = (const int*)d_in[1];
    const int*   batch   = (const int*)d_in[2];
    const int*   cluster = (const int*)d_in[3];
    const int*   gei     = (const int*)d_in[4];
    const float* emb     = (const float*)d_in[5];
    const float* w1      = (const float*)d_in[6];
    const float* b1      = (const float*)d_in[7];
    const float* g1      = (const float*)d_in[8];
    const float* be1     = (const float*)d_in[9];
    const float* w2      = (const float*)d_in[10];
    const float* b2      = (const float*)d_in[11];
    const float* g2      = (const float*)d_in[12];
    const float* be2     = (const float*)d_in[13];
    const float* wm      = (const float*)d_in[14];
    const float* bm      = (const float*)d_in[15];
    float* out = (float*)d_out;

    float *agg, *h1, *h2, *y, *y2, *scale, *shift;
    unsigned char* zb;
    int *rowptr, *cur, *colidx;
    int *nstart, *gstart, *ybatch, *psum, *poff;
    cudaGetSymbolAddress((void**)&agg,     g_agg);
    cudaGetSymbolAddress((void**)&h1,      g_h1);
    cudaGetSymbolAddress((void**)&h2,      g_h2);
    cudaGetSymbolAddress((void**)&y,       g_y);
    cudaGetSymbolAddress((void**)&y2,      g_y2);
    cudaGetSymbolAddress((void**)&zb,      g_zerobuf);
    cudaGetSymbolAddress((void**)&rowptr,  g_rowptr);
    cudaGetSymbolAddress((void**)&cur,     g_cur);
    cudaGetSymbolAddress((void**)&colidx,  g_colidx);
    cudaGetSymbolAddress((void**)&nstart,  g_nstart);
    cudaGetSymbolAddress((void**)&gstart,  g_gstart);
    cudaGetSymbolAddress((void**)&ybatch,  g_ybatch);
    cudaGetSymbolAddress((void**)&psum,    g_psum);
    cudaGetSymbolAddress((void**)&poff,    g_poff);
    cudaGetSymbolAddress((void**)&scale,   g_scale);
    cudaGetSymbolAddress((void**)&shift,   g_shift);

    int* cnt = (int*)zb;
    double* stats = (double*)(zb + CNT_BYTES);

    const int T = 256;

    // ---- zero counters + stats in ONE memset ----
    cudaMemsetAsync(zb, 0, ZERO_BYTES);

    // ---- combined CSR build (nodes + clusters) ----
    k_hist<<<cdiv(NEALL, T), T>>>(ei, gei, cnt);
    k_scan1<<<cdiv(NSEG, 1024), 256>>>(cnt, rowptr, psum, NSEG);
    k_scan2<<<1, 128>>>(psum, poff, cdiv(NSEG, 1024));
    k_scan3<<<cdiv(NSEG, T), T>>>(rowptr, cur, poff, NSEG, NEALL);
    k_ticket<<<cdiv(NEALL, T), T>>>(ei, gei, cur, colidx);

    // ---- segment boundaries (sorted cluster ids) ----
    k_bound<<<cdiv(NN, T), T>>>(cluster, NN, NC, nstart);

    // ---- layer 1: conv(64 -> 80); h-half read directly from emb[x[n]] ----
    k_gather_emb<<<cdiv(NN * 32, T), T>>>(rowptr, colidx, x, emb, agg);
    k_gemm_tc<128, 64, 64, 80, 80, true, false, true><<<dim3(cdiv(NN, 128), 1), T>>>(
        agg, nullptr, x, emb, w1, b1, h1, NN, stats, nullptr, nullptr);
    k_bnfin<<<1, 128>>>(stats, g1, be1, scale, shift, 80, NN);

    // ---- layer 2: conv(80 -> 96), BN1 folded into gather + z-load ----
    k_gather_bn80<<<cdiv(NN * 32, T), T>>>(rowptr, colidx, h1, scale, shift, agg);
    k_gemm_tc<160, 80, 80, 96, 96, true, true, false><<<dim3(cdiv(NN, 128), 1), T>>>(
        agg, h1, nullptr, nullptr, w2, b2, h2, NN, stats + LSTRIDE, scale, shift);
    k_bnfin<<<1, 128>>>(stats + LSTRIDE, g2, be2, scale + 96, shift + 96, 96, NN);

    // ---- cluster max-pool with BN2 fold (sign-safe) + ybatch ----
    k_pool<<<NC, 128>>>(h2, nstart, batch, scale + 96, shift + 96, y, ybatch);
    k_bound<<<cdiv(NC, T), T>>>(ybatch, NC, NG, gstart);

    // ---- global conv(96 -> 256): cluster CSR lives at combined offset NN ----
    k_gather96<<<cdiv(NC * 32, T), T>>>(rowptr + NN, colidx, y, agg, NC);
    k_gemm_tc<192, 96, 96, 256, 128, false, false, false><<<dim3(cdiv(NC, 128), 2), T>>>(
        agg, y, nullptr, nullptr, wm, bm, y2, NC, nullptr, nullptr, nullptr);

    // ---- graph max-pool -> output ----
    k_final<<<NG, 256>>>(y2, gstart, out);
}

// round 7
// speedup vs baseline: 1.8319x; 1.0144x over previous
#include <cuda_runtime.h>
#include <cfloat>
#include <math.h>

// ---------------- problem constants ----------------
#define NN   100000   // nodes
#define NE   800000   // edges
#define NC   20000    // clusters
#define NGE  320000   // global edges
#define NG   256      // graphs
#define EPSB 1e-5f
#define NSEG (NN + NC)
#define NEALL (NE + NGE)
#define SLOT8 8
#define SQOFF (256 * SLOT8)         // sumsq offset within a layer region (doubles)
#define LSTRIDE (512 * SLOT8)       // doubles per layer region
#define CNT_BYTES (NSEG * 4)        // 480000, 16B-aligned
#define ZERO_BYTES (CNT_BYTES + 2 * LSTRIDE * 8)

// ---------------- scratch (device globals) ----------------
__device__ __align__(16) float  g_agg[NN * 96];
__device__ __align__(16) float  g_h1[NN * 80];
__device__ __align__(16) float  g_h2[NN * 96];
__device__ __align__(16) float  g_y [NC * 96];
__device__ __align__(16) float  g_y2[NC * 256];
__device__ __align__(16) unsigned char g_zerobuf[ZERO_BYTES];   // [cnt | stats]
__device__ __align__(16) int    g_rowptr[NSEG + 1];
__device__ __align__(16) int    g_cur[NSEG];
__device__ __align__(16) int    g_colidx[NEALL];
__device__ int    g_nstart[NC + 1];
__device__ int    g_gstart[NG + 1];
__device__ int    g_ybatch[NC];
__device__ int    g_psum[128];
__device__ int    g_poff[128];
__device__ __align__(16) float  g_scale[256];
__device__ __align__(16) float  g_shift[256];

// ---------------- tf32 / mma helpers ----------------
__device__ __forceinline__ unsigned tf32cvt(float f) {
    unsigned u;
    asm("cvt.rna.tf32.f32 %0, %1;" : "=r"(u) : "f"(f));
    return u;
}
__device__ __forceinline__ void mma_tf32(float4& d, uint2 a01, uint2 a23, uint2 b) {
    asm volatile(
        "mma.sync.aligned.m16n8k8.row.col.f32.tf32.tf32.f32 "
        "{%0,%1,%2,%3}, {%4,%5,%6,%7}, {%8,%9}, {%0,%1,%2,%3};"
        : "+f"(d.x), "+f"(d.y), "+f"(d.z), "+f"(d.w)
        : "r"(a01.x), "r"(a01.y), "r"(a23.x), "r"(a23.y), "r"(b.x), "r"(b.y));
}

// ---------------- CSR build (combined node+cluster): hist -> scan -> ticket ----------------
__global__ void k_hist(const int* __restrict__ ei, const int* __restrict__ gei,
                       int* __restrict__ cnt) {
    int i = blockIdx.x * blockDim.x + threadIdx.x;
    if (i < NE) atomicAdd(&cnt[ei[NE + i]], 1);
    else if (i < NEALL) atomicAdd(&cnt[NN + gei[NGE + (i - NE)]], 1);
}

__global__ void k_scan1(const int* __restrict__ cnt, int* __restrict__ loc,
                        int* __restrict__ psum, int n) {
    __shared__ int sh[256];
    int t = threadIdx.x;
    int idx = blockIdx.x * 1024 + t * 4;
    int a0 = 0, a1 = 0, a2 = 0, a3 = 0;
    if (idx + 3 < n) {
        int4 q = *reinterpret_cast<const int4*>(cnt + idx);
        a0 = q.x; a1 = q.y; a2 = q.z; a3 = q.w;
    } else {
        if (idx     < n) a0 = cnt[idx];
        if (idx + 1 < n) a1 = cnt[idx + 1];
        if (idx + 2 < n) a2 = cnt[idx + 2];
    }
    int s = a0 + a1 + a2 + a3;
    sh[t] = s; __syncthreads();
    for (int off = 1; off < 256; off <<= 1) {
        int u = (t >= off) ? sh[t - off] : 0;
        __syncthreads(); sh[t] += u; __syncthreads();
    }
    int excl = sh[t] - s;
    if (idx     < n) loc[idx]     = excl;
    if (idx + 1 < n) loc[idx + 1] = excl + a0;
    if (idx + 2 < n) loc[idx + 2] = excl + a0 + a1;
    if (idx + 3 < n) loc[idx + 3] = excl + a0 + a1 + a2;
    if (t == 255) psum[blockIdx.x] = sh[t];
}

__global__ void k_scan2(const int* __restrict__ psum, int* __restrict__ poff, int nb) {
    __shared__ int sh[128];
    int t = threadIdx.x;
    int v = (t < nb) ? psum[t] : 0;
    sh[t] = v; __syncthreads();
    for (int off = 1; off < 128; off <<= 1) {
        int u = (t >= off) ? sh[t - off] : 0;
        __syncthreads(); sh[t] += u; __syncthreads();
    }
    if (t < nb) poff[t] = sh[t] - v;
}

__global__ void k_scan3(int* __restrict__ rowptr, int* __restrict__ cur,
                        const int* __restrict__ poff, int n, int total) {
    int i = blockIdx.x * blockDim.x + threadIdx.x;
    if (i < n) {
        int v = rowptr[i] + poff[i >> 10];
        rowptr[i] = v;
        cur[i] = v;
    }
    if (i == 0) rowptr[n] = total;
}

__global__ void k_ticket(const int* __restrict__ ei, const int* __restrict__ gei,
                         int* __restrict__ cur, int* __restrict__ colidx) {
    int i = blockIdx.x * blockDim.x + threadIdx.x;
    if (i < NE) {
        int p = atomicAdd(&cur[ei[NE + i]], 1);
        colidx[p] = ei[i];
    } else if (i < NEALL) {
        int e = i - NE;
        int p = atomicAdd(&cur[NN + gei[NGE + e]], 1);
        colidx[p] = gei[e];
    }
}

// ---------------- gather aggregations (float4 rows, unroll x4) ----------------
// agg1[n] = sum emb[x[src]]; 16-lane half-warp per node, one float4 per lane.
__global__ void k_gather_emb(const int* __restrict__ rowptr, const int* __restrict__ colidx,
                             const int* __restrict__ x, const float* __restrict__ emb,
                             float* __restrict__ agg) {
    int gid = blockIdx.x * blockDim.x + threadIdx.x;
    int w = gid >> 4;                    // node
    int lane = threadIdx.x & 15;         // float4 chunk (64 floats = 16 chunks)
    if (w >= NN) return;
    int s0 = rowptr[w], s1 = rowptr[w + 1];
    const float4* e4 = reinterpret_cast<const float4*>(emb);
    float4 acc = make_float4(0.f, 0.f, 0.f, 0.f);
    int e = s0;
    for (; e + 3 < s1; e += 4) {
        int i0 = x[colidx[e]] * 16,     i1 = x[colidx[e + 1]] * 16;
        int i2 = x[colidx[e + 2]] * 16, i3 = x[colidx[e + 3]] * 16;
        float4 v0 = e4[i0 + lane], v1 = e4[i1 + lane];
        float4 v2 = e4[i2 + lane], v3 = e4[i3 + lane];
        acc.x += (v0.x + v1.x) + (v2.x + v3.x);
        acc.y += (v0.y + v1.y) + (v2.y + v3.y);
        acc.z += (v0.z + v1.z) + (v2.z + v3.z);
        acc.w += (v0.w + v1.w) + (v2.w + v3.w);
    }
    for (; e < s1; ++e) {
        float4 v = e4[x[colidx[e]] * 16 + lane];
        acc.x += v.x; acc.y += v.y; acc.z += v.z; acc.w += v.w;
    }
    reinterpret_cast<float4*>(agg)[w * 16 + lane] = acc;
}

// agg2[n] = scale*(sum h1[src]) + deg*shift  (BN1 fold; D=80 = 20 float4 lanes)
__global__ void k_gather_bn80(const int* __restrict__ rowptr, const int* __restrict__ colidx,
                              const float* __restrict__ h1, const float* __restrict__ scale,
                              const float* __restrict__ shift, float* __restrict__ agg) {
    int w = (blockIdx.x * blockDim.x + threadIdx.x) >> 5;
    int lane = threadIdx.x & 31;
    if (w >= NN) return;
    int s0 = rowptr[w], s1 = rowptr[w + 1];
    const float4* h4 = reinterpret_cast<const float4*>(h1);
    float4 acc = make_float4(0.f, 0.f, 0.f, 0.f);
    bool act = lane < 20;
    int e = s0;
    for (; e + 3 < s1; e += 4) {
        int i0 = colidx[e] * 20,     i1 = colidx[e + 1] * 20;
        int i2 = colidx[e + 2] * 20, i3 = colidx[e + 3] * 20;
        if (act) {
            float4 v0 = h4[i0 + lane], v1 = h4[i1 + lane];
            float4 v2 = h4[i2 + lane], v3 = h4[i3 + lane];
            acc.x += (v0.x + v1.x) + (v2.x + v3.x);
            acc.y += (v0.y + v1.y) + (v2.y + v3.y);
            acc.z += (v0.z + v1.z) + (v2.z + v3.z);
            acc.w += (v0.w + v1.w) + (v2.w + v3.w);
        }
    }
    for (; e < s1; ++e) {
        if (act) {
            float4 v = h4[colidx[e] * 20 + lane];
            acc.x += v.x; acc.y += v.y; acc.z += v.z; acc.w += v.w;
        }
    }
    if (act) {
        float deg = (float)(s1 - s0);
        float4 sc = reinterpret_cast<const float4*>(scale)[lane];
        float4 sh = reinterpret_cast<const float4*>(shift)[lane];
        float4 r;
        r.x = fmaf(acc.x, sc.x, deg * sh.x);
        r.y = fmaf(acc.y, sc.y, deg * sh.y);
        r.z = fmaf(acc.z, sc.z, deg * sh.z);
        r.w = fmaf(acc.w, sc.w, deg * sh.w);
        reinterpret_cast<float4*>(agg)[w * 20 + lane] = r;
    }
}

// agg3[c] = sum y[src]  (D=96 = 24 float4 lanes)
__global__ void k_gather96(const int* __restrict__ rowptr, const int* __restrict__ colidx,
                           const float* __restrict__ src, float* __restrict__ agg, int N) {
    int w = (blockIdx.x * blockDim.x + threadIdx.x) >> 5;
    int lane = threadIdx.x & 31;
    if (w >= N) return;
    int s0 = rowptr[w], s1 = rowptr[w + 1];
    const float4* s4 = reinterpret_cast<const float4*>(src);
    float4 acc = make_float4(0.f, 0.f, 0.f, 0.f);
    bool act = lane < 24;
    int e = s0;
    for (; e + 3 < s1; e += 4) {
        int i0 = colidx[e] * 24,     i1 = colidx[e + 1] * 24;
        int i2 = colidx[e + 2] * 24, i3 = colidx[e + 3] * 24;
        if (act) {
            float4 v0 = s4[i0 + lane], v1 = s4[i1 + lane];
            float4 v2 = s4[i2 + lane], v3 = s4[i3 + lane];
            acc.x += (v0.x + v1.x) + (v2.x + v3.x);
            acc.y += (v0.y + v1.y) + (v2.y + v3.y);
            acc.z += (v0.z + v1.z) + (v2.z + v3.z);
            acc.w += (v0.w + v1.w) + (v2.w + v3.w);
        }
    }
    for (; e < s1; ++e) {
        if (act) {
            float4 v = s4[colidx[e] * 24 + lane];
            acc.x += v.x; acc.y += v.y; acc.z += v.z; acc.w += v.w;
        }
    }
    if (act) reinterpret_cast<float4*>(agg)[w * 24 + lane] = acc;
}

// ---------------- segment boundaries (sorted segment ids) ----------------
__global__ void k_bound(const int* __restrict__ seg, int n, int nseg,
                        int* __restrict__ start) {
    int i = blockIdx.x * blockDim.x + threadIdx.x;
    if (i == 0) { start[0] = 0; start[nseg] = n; }
    else if (i < n) {
        int c0 = seg[i - 1], c1 = seg[i];
        for (int c = c0 + 1; c <= c1; ++c) start[c] = i;
    }
}

// cluster pool: y[c][f] = BN2( segment-max over nodes of h2 ), sign-safe fold.
__global__ void __launch_bounds__(128)
k_pool(const float* __restrict__ h2, const int* __restrict__ nstart,
       const int* __restrict__ batch, const float* __restrict__ scale,
       const float* __restrict__ shift, float* __restrict__ y, int* __restrict__ ybatch) {
    int c = blockIdx.x;
    int t = threadIdx.x;
    int ns = nstart[c], ne = nstart[c + 1];
    if (t < 96) {
        float mx = -FLT_MAX, mn = FLT_MAX;
        for (int n = ns; n < ne; ++n) {
            float v = h2[(size_t)n * 96 + t];
            mx = fmaxf(mx, v); mn = fminf(mn, v);
        }
        float sc = scale[t];
        y[(size_t)c * 96 + t] = fmaf(sc >= 0.f ? mx : mn, sc, shift[t]);
    } else if (t == 96 && ne > ns) {
        ybatch[c] = batch[ne - 1];
    }
}

// final pool: out[g][f] = max over clusters of y2
__global__ void __launch_bounds__(256)
k_final(const float* __restrict__ y2, const int* __restrict__ gstart,
        float* __restrict__ out) {
    int g = blockIdx.x;
    int f = threadIdx.x;
    int gs = gstart[g], ge = gstart[g + 1];
    float mx = -FLT_MAX;
    for (int c = gs; c < ge; ++c)
        mx = fmaxf(mx, y2[(size_t)c * 256 + f]);
    out[(size_t)g * 256 + f] = mx;
}

// ---------------- TF32 tensor-core GEMM (+relu, +BN stats) ----------------
template <int K, int DAGG, int DH, int MTOT, int MCHUNK, bool STATS, bool BNZ, bool EMB>
__global__ void __launch_bounds__(256)
k_gemm_tc(const float* __restrict__ agg, const float* __restrict__ h,
          const int* __restrict__ x, const float* __restrict__ emb,
          const float* __restrict__ W, const float* __restrict__ bias,
          float* __restrict__ out, int N, double* __restrict__ stats,
          const float* __restrict__ zsc, const float* __restrict__ zsh) {
    constexpr int NK    = K / 32;
    constexpr int NSPAN = MCHUNK / 2;
    constexpr int NT    = NSPAN / 8;
    constexpr int ZS    = 136;
    constexpr int WS    = 40;
    static_assert(K % 32 == 0 && MCHUNK % 16 == 0, "tile shape");

    __shared__ unsigned z_s[32 * ZS];
    __shared__ unsigned w_s[MCHUNK * WS];

    const int t     = threadIdx.x;
    const int lane  = t & 31;
    const int wid   = t >> 5;
    const int wm    = wid & 3;
    const int wn    = wid >> 2;
    const int gr    = lane >> 2;
    const int tc    = lane & 3;
    const int nbase = blockIdx.x * 128;
    const int cbase = blockIdx.y * MCHUNK;

    float4 acc[2][NT];
#pragma unroll
    for (int mt = 0; mt < 2; ++mt)
#pragma unroll
        for (int nt = 0; nt < NT; ++nt) acc[mt][nt] = make_float4(0.f, 0.f, 0.f, 0.f);

    for (int c = 0; c < NK; ++c) {
#pragma unroll
        for (int r = 0; r < 16; ++r) {
            int idx = t + r * 256;
            int kk = idx & 31, n = idx >> 5;
            int node = nbase + n;
            int k = c * 32 + kk;
            float v = 0.f;
            if (node < N) {
                if (k < DAGG) v = agg[(size_t)node * DAGG + k];
                else if (EMB) v = emb[x[node] * DH + (k - DAGG)];
                else {
                    float hv = h[(size_t)node * DH + (k - DAGG)];
                    v = BNZ ? fmaf(hv, zsc[k - DAGG], zsh[k - DAGG]) : hv;
                }
            }
            int np = (n & 0x70) | ((n & 7) << 1) | ((n >> 3) & 1);
            z_s[kk * ZS + np] = tf32cvt(v);
        }
#pragma unroll
        for (int idx = t; idx < 32 * MCHUNK; idx += 256) {
            int kk = idx & 31, j = idx >> 5;
            float wv = W[(size_t)(cbase + j) * K + c * 32 + kk];
            int kp = (kk & ~7) | ((kk & 3) << 1) | ((kk & 4) >> 2);
            w_s[j * WS + kp] = tf32cvt(wv);
        }
        __syncthreads();

#pragma unroll
        for (int g = 0; g < 4; ++g) {
            uint2 a01[2], a23[2];
#pragma unroll
            for (int mt = 0; mt < 2; ++mt) {
                int col = wm * 32 + mt * 16 + 2 * gr;
                a01[mt] = *reinterpret_cast<const uint2*>(&z_s[(g * 8 + tc) * ZS + col]);
                a23[mt] = *reinterpret_cast<const uint2*>(&z_s[(g * 8 + tc + 4) * ZS + col]);
            }
#pragma unroll
            for (int nt = 0; nt < NT; ++nt) {
                uint2 b = *reinterpret_cast<const uint2*>(
                    &w_s[(wn * NSPAN + nt * 8 + gr) * WS + g * 8 + tc * 2]);
                mma_tf32(acc[0][nt], a01[0], a23[0], b);
                mma_tf32(acc[1][nt], a01[1], a23[1], b);
            }
        }
        __syncthreads();
    }

    const int slot = blockIdx.x & (SLOT8 - 1);
#pragma unroll
    for (int nt = 0; nt < NT; ++nt) {
        int col = cbase + wn * NSPAN + nt * 8 + 2 * tc;
        float b0 = bias[col], b1 = bias[col + 1];
        float s0 = 0.f, s1 = 0.f, q0 = 0.f, q1 = 0.f;
#pragma unroll
        for (int mt = 0; mt < 2; ++mt) {
            int node0 = nbase + wm * 32 + mt * 16 + gr;
            int node1 = node0 + 8;
            float4 a = acc[mt][nt];
            float r00 = fmaxf(a.x + b0, 0.f);
            float r01 = fmaxf(a.y + b1, 0.f);
            float r10 = fmaxf(a.z + b0, 0.f);
            float r11 = fmaxf(a.w + b1, 0.f);
            if (node0 < N) {
                *reinterpret_cast<float2*>(&out[(size_t)node0 * MTOT + col]) =
                    make_float2(r00, r01);
                s0 += r00; q0 += r00 * r00;
                s1 += r01; q1 += r01 * r01;
            }
            if (node1 < N) {
                *reinterpret_cast<float2*>(&out[(size_t)node1 * MTOT + col]) =
                    make_float2(r10, r11);
                s0 += r10; q0 += r10 * r10;
                s1 += r11; q1 += r11 * r11;
            }
        }
        if (STATS) {
#pragma unroll
            for (int off = 4; off < 32; off <<= 1) {
                s0 += __shfl_xor_sync(0xffffffffu, s0, off);
                s1 += __shfl_xor_sync(0xffffffffu, s1, off);
                q0 += __shfl_xor_sync(0xffffffffu, q0, off);
                q1 += __shfl_xor_sync(0xffffffffu, q1, off);
            }
            if (gr == 0) {
                atomicAdd(&stats[col * SLOT8 + slot], (double)s0);
                atomicAdd(&stats[(col + 1) * SLOT8 + slot], (double)s1);
                atomicAdd(&stats[SQOFF + col * SLOT8 + slot], (double)q0);
                atomicAdd(&stats[SQOFF + (col + 1) * SLOT8 + slot], (double)q1);
            }
        }
    }
}

// BN finalize: reduce 8 slots, biased variance
__global__ void k_bnfin(const double* __restrict__ stats, const float* __restrict__ g,
                        const float* __restrict__ be, float* __restrict__ scale,
                        float* __restrict__ shift, int M, int N) {
    int j = blockIdx.x * blockDim.x + threadIdx.x;
    if (j < M) {
        double s = 0.0, s2 = 0.0;
#pragma unroll
        for (int k = 0; k < SLOT8; ++k) {
            s  += stats[j * SLOT8 + k];
            s2 += stats[SQOFF + j * SLOT8 + k];
        }
        double inv = 1.0 / (double)N;
        float mean = (float)(s * inv);
        float var  = (float)(s2 * inv) - mean * mean;
        float sc   = rsqrtf(var + EPSB) * g[j];
        scale[j] = sc;
        shift[j] = be[j] - mean * sc;
    }
}

// ---------------- launch ----------------
static inline int cdiv(int a, int b) { return (a + b - 1) / b; }

extern "C" void kernel_launch(void* const* d_in, const int* in_sizes, int n_in,
                              void* d_out, int out_size) {
    (void)in_sizes; (void)n_in; (void)out_size;
    const int*   x       = (const int*)d_in[0];
    const int*   ei      = (const int*)d_in[1];
    const int*   batch   = (const int*)d_in[2];
    const int*   cluster = (const int*)d_in[3];
    const int*   gei     = (const int*)d_in[4];
    const float* emb     = (const float*)d_in[5];
    const float* w1      = (const float*)d_in[6];
    const float* b1      = (const float*)d_in[7];
    const float* g1      = (const float*)d_in[8];
    const float* be1     = (const float*)d_in[9];
    const float* w2      = (const float*)d_in[10];
    const float* b2      = (const float*)d_in[11];
    const float* g2      = (const float*)d_in[12];
    const float* be2     = (const float*)d_in[13];
    const float* wm      = (const float*)d_in[14];
    const float* bm      = (const float*)d_in[15];
    float* out = (float*)d_out;

    float *agg, *h1, *h2, *y, *y2, *scale, *shift;
    unsigned char* zb;
    int *rowptr, *cur, *colidx;
    int *nstart, *gstart, *ybatch, *psum, *poff;
    cudaGetSymbolAddress((void**)&agg,     g_agg);
    cudaGetSymbolAddress((void**)&h1,      g_h1);
    cudaGetSymbolAddress((void**)&h2,      g_h2);
    cudaGetSymbolAddress((void**)&y,       g_y);
    cudaGetSymbolAddress((void**)&y2,      g_y2);
    cudaGetSymbolAddress((void**)&zb,      g_zerobuf);
    cudaGetSymbolAddress((void**)&rowptr,  g_rowptr);
    cudaGetSymbolAddress((void**)&cur,     g_cur);
    cudaGetSymbolAddress((void**)&colidx,  g_colidx);
    cudaGetSymbolAddress((void**)&nstart,  g_nstart);
    cudaGetSymbolAddress((void**)&gstart,  g_gstart);
    cudaGetSymbolAddress((void**)&ybatch,  g_ybatch);
    cudaGetSymbolAddress((void**)&psum,    g_psum);
    cudaGetSymbolAddress((void**)&poff,    g_poff);
    cudaGetSymbolAddress((void**)&scale,   g_scale);
    cudaGetSymbolAddress((void**)&shift,   g_shift);

    int* cnt = (int*)zb;
    double* stats = (double*)(zb + CNT_BYTES);

    const int T = 256;

    // ---- zero counters + stats in ONE memset ----
    cudaMemsetAsync(zb, 0, ZERO_BYTES);

    // ---- combined CSR build (nodes + clusters) ----
    k_hist<<<cdiv(NEALL, T), T>>>(ei, gei, cnt);
    k_scan1<<<cdiv(NSEG, 1024), 256>>>(cnt, rowptr, psum, NSEG);
    k_scan2<<<1, 128>>>(psum, poff, cdiv(NSEG, 1024));
    k_scan3<<<cdiv(NSEG, T), T>>>(rowptr, cur, poff, NSEG, NEALL);
    k_ticket<<<cdiv(NEALL, T), T>>>(ei, gei, cur, colidx);

    // ---- layer 1: conv(64 -> 80); h-half read directly from emb[x[n]] ----
    k_gather_emb<<<cdiv(NN * 16, T), T>>>(rowptr, colidx, x, emb, agg);
    k_gemm_tc<128, 64, 64, 80, 80, true, false, true><<<dim3(cdiv(NN, 128), 1), T>>>(
        agg, nullptr, x, emb, w1, b1, h1, NN, stats, nullptr, nullptr);
    k_bnfin<<<1, 128>>>(stats, g1, be1, scale, shift, 80, NN);

    // ---- layer 2: conv(80 -> 96), BN1 folded into gather + z-load ----
    k_gather_bn80<<<cdiv(NN * 32, T), T>>>(rowptr, colidx, h1, scale, shift, agg);
    k_gemm_tc<160, 80, 80, 96, 96, true, true, false><<<dim3(cdiv(NN, 128), 1), T>>>(
        agg, h1, nullptr, nullptr, w2, b2, h2, NN, stats + LSTRIDE, scale, shift);
    k_bnfin<<<1, 128>>>(stats + LSTRIDE, g2, be2, scale + 96, shift + 96, 96, NN);

    // ---- cluster max-pool with BN2 fold (sign-safe) + ybatch ----
    k_bound<<<cdiv(NN, T), T>>>(cluster, NN, NC, nstart);
    k_pool<<<NC, 128>>>(h2, nstart, batch, scale + 96, shift + 96, y, ybatch);
    k_bound<<<cdiv(NC, T), T>>>(ybatch, NC, NG, gstart);

    // ---- global conv(96 -> 256): cluster CSR lives at combined offset NN ----
    k_gather96<<<cdiv(NC * 32, T), T>>>(rowptr + NN, colidx, y, agg, NC);
    k_gemm_tc<192, 96, 96, 256, 128, false, false, false><<<dim3(cdiv(NC, 128), 2), T>>>(
        agg, y, nullptr, nullptr, wm, bm, y2, NC, nullptr, nullptr, nullptr);

    // ---- graph max-pool -> output ----
    k_final<<<NG, 256>>>(y2, gstart, out);
}